// round 5
// baseline (speedup 1.0000x reference)
#include <cuda_runtime.h>
#include <math.h>
#include <stdint.h>

#define B_  2
#define T_  2048
#define C_  1024
#define H_  16
#define D_  64
#define BH_ 32
#define M_  4096
#define N3_ 3072
#define K_  1024

// ---------------- scratch (__device__ globals; no allocs allowed) ----------
__device__ float g_q[BH_*T_*D_];
__device__ float g_k[BH_*T_*D_];
__device__ float g_v[BH_*T_*D_];
__device__ float g_y[M_*C_];
__device__ float g_cos[T_*32];
__device__ float g_sin[T_*32];

// ---------------- RoPE table ------------------------------------------------
__global__ void rope_table_kernel() {
    int idx = blockIdx.x * 256 + threadIdx.x;   // 65536 = 2048*32
    int t = idx >> 5, i = idx & 31;
    double inv = pow(10000.0, -(double)(2 * i) / 64.0);
    float ff = (float)t * (float)inv;           // match reference fp32 rounding
    double s, c;
    sincos((double)ff, &s, &c);
    g_cos[idx] = (float)c;
    g_sin[idx] = (float)s;
}

// ---------------- tf32 helpers ----------------------------------------------
__device__ __forceinline__ uint32_t f2tf32(float f) {
    uint32_t u;
    asm("cvt.rna.tf32.f32 %0, %1;" : "=r"(u) : "f"(f));
    return u;
}

__device__ __forceinline__ void mma_tf32(float c[4], const uint32_t a[4],
                                         const uint32_t b[2]) {
    asm volatile(
        "mma.sync.aligned.m16n8k8.row.col.f32.tf32.tf32.f32 "
        "{%0,%1,%2,%3}, {%4,%5,%6,%7}, {%8,%9}, {%0,%1,%2,%3};"
        : "+f"(c[0]), "+f"(c[1]), "+f"(c[2]), "+f"(c[3])
        : "r"(a[0]), "r"(a[1]), "r"(a[2]), "r"(a[3]), "r"(b[0]), "r"(b[1]));
}

// ---------------- 3-pass split-tf32 warp-MMA GEMM ---------------------------
// C[M,N] = A[M,K] @ W[K,N], error ~fp32 (split: Ah*Bh + Al*Bh + Ah*Bl).
// 128x128 CTA tile, KCHUNK=32, 256 threads, 8 warps (2x4 of 64x32 warp tiles).
// MODE 0: A=x (param), W=w_qkv -> scatters q/k/v [B,H,T,D] with RoPE.
// MODE 1: A=g_y (DEVICE-side!), W=w_proj -> adds bias, writes out.
#define SST 136   // smem row stride (words); 136 % 32 == 8 -> conflict-free
#define TILE_W   (32 * SST)                     // words per tile
#define GEMM_SMEM_BYTES (4 * TILE_W * 4)        // 69,632 B (Ah, Al, Bh, Bl)

template <int MODE>
__global__ __launch_bounds__(256) void gemm_tf32(
    const float* __restrict__ Ain, const float* __restrict__ W,
    const float* __restrict__ bias, float* __restrict__ out)
{
    const int N = MODE ? C_ : N3_;
    extern __shared__ uint32_t dsm[];
    uint32_t (*Ah)[SST] = (uint32_t(*)[SST])(dsm);
    uint32_t (*Al)[SST] = (uint32_t(*)[SST])(dsm + TILE_W);
    uint32_t (*Bh)[SST] = (uint32_t(*)[SST])(dsm + 2 * TILE_W);
    uint32_t (*Bl)[SST] = (uint32_t(*)[SST])(dsm + 3 * TILE_W);

    // CRITICAL: __device__ symbol taken on DEVICE side (R4 bug: host-side
    // g_y gave the host shadow address; ATS read host zeros -> out==0).
    const float* A = MODE ? (const float*)g_y : Ain;

    const int tid  = threadIdx.x;
    const int wid  = tid >> 5;
    const int lane = tid & 31;
    const int g  = lane >> 2;       // group id 0..7
    const int tq = lane & 3;        // thread-in-group 0..3
    const int wm = wid >> 2;        // 0..1  (m offset wm*64)
    const int wn = wid & 3;         // 0..3  (n offset wn*32)
    const int m0 = blockIdx.y * 128;
    const int n0 = blockIdx.x * 128;

    float acc[4][4][4] = {};        // [mfrag][nfrag][reg]

    for (int kk = 0; kk < K_; kk += 32) {
        // A tile (128 m x 32 k) -> transpose into Ah/Al[k][m] (hi/lo tf32)
        #pragma unroll
        for (int i = 0; i < 4; i++) {
            int q = i * 256 + tid;          // 1024 float4s
            int m = q >> 3, j = (q & 7) << 2;
            float4 v = *(const float4*)(A + (size_t)(m0 + m) * K_ + kk + j);
            float vv[4] = {v.x, v.y, v.z, v.w};
            #pragma unroll
            for (int c = 0; c < 4; c++) {
                uint32_t h = f2tf32(vv[c]);
                Ah[j + c][m] = h;
                Al[j + c][m] = f2tf32(vv[c] - __uint_as_float(h));
            }
        }
        // W tile (32 k x 128 n) -> Bh/Bl[k][n]
        #pragma unroll
        for (int i = 0; i < 4; i++) {
            int q = i * 256 + tid;          // 1024 float4s
            int k = q >> 5, j = (q & 31) << 2;
            float4 v = *(const float4*)(W + (size_t)(kk + k) * N + n0 + j);
            uint4 uh, ul;
            uh.x = f2tf32(v.x); ul.x = f2tf32(v.x - __uint_as_float(uh.x));
            uh.y = f2tf32(v.y); ul.y = f2tf32(v.y - __uint_as_float(uh.y));
            uh.z = f2tf32(v.z); ul.z = f2tf32(v.z - __uint_as_float(uh.z));
            uh.w = f2tf32(v.w); ul.w = f2tf32(v.w - __uint_as_float(uh.w));
            *(uint4*)&Bh[k][j] = uh;
            *(uint4*)&Bl[k][j] = ul;
        }
        __syncthreads();

        #pragma unroll
        for (int k8 = 0; k8 < 4; k8++) {
            const int k0 = k8 * 8;
            uint32_t ah[4][4], al[4][4], bh[4][2], bl[4][2];
            #pragma unroll
            for (int mi = 0; mi < 4; mi++) {
                int mb = wm * 64 + mi * 16 + g;
                ah[mi][0] = Ah[k0 + tq][mb];
                ah[mi][1] = Ah[k0 + tq][mb + 8];
                ah[mi][2] = Ah[k0 + tq + 4][mb];
                ah[mi][3] = Ah[k0 + tq + 4][mb + 8];
                al[mi][0] = Al[k0 + tq][mb];
                al[mi][1] = Al[k0 + tq][mb + 8];
                al[mi][2] = Al[k0 + tq + 4][mb];
                al[mi][3] = Al[k0 + tq + 4][mb + 8];
            }
            #pragma unroll
            for (int ni = 0; ni < 4; ni++) {
                int nb = wn * 32 + ni * 8 + g;
                bh[ni][0] = Bh[k0 + tq][nb];
                bh[ni][1] = Bh[k0 + tq + 4][nb];
                bl[ni][0] = Bl[k0 + tq][nb];
                bl[ni][1] = Bl[k0 + tq + 4][nb];
            }
            #pragma unroll
            for (int mi = 0; mi < 4; mi++)
                #pragma unroll
                for (int ni = 0; ni < 4; ni++) {
                    mma_tf32(acc[mi][ni], ah[mi], bh[ni]);
                    mma_tf32(acc[mi][ni], al[mi], bh[ni]);
                    mma_tf32(acc[mi][ni], ah[mi], bl[ni]);
                }
        }
        __syncthreads();
    }

    // ------------- epilogue -------------
    #pragma unroll
    for (int mi = 0; mi < 4; mi++) {
        #pragma unroll
        for (int ni = 0; ni < 4; ni++) {
            const float* c = acc[mi][ni];
            int r0 = m0 + wm * 64 + mi * 16 + g;     // rows r0, r0+8
            int nc = n0 + wn * 32 + ni * 8 + 2 * tq; // cols nc (even), nc+1
            #pragma unroll
            for (int half = 0; half < 2; half++) {
                int m = r0 + half * 8;
                float e = c[half * 2 + 0];
                float o = c[half * 2 + 1];
                if (MODE == 0) {
                    int b = m >> 11, t = m & 2047;
                    int sec = nc >> 10, cc = nc & 1023;
                    int h = cc >> 6, d = cc & 63;    // d even
                    size_t base = ((size_t)((b << 4) + h) * T_ + t) * D_ + d;
                    if (sec == 2) {
                        *(float2*)(g_v + base) = make_float2(e, o);
                    } else {
                        float co = g_cos[t * 32 + (d >> 1)];
                        float si = g_sin[t * 32 + (d >> 1)];
                        float oe = e * co - o * si;
                        float oo = e * si + o * co;
                        if (sec == 0)
                            *(float2*)(g_q + base) = make_float2(oe * 0.125f, oo * 0.125f);
                        else
                            *(float2*)(g_k + base) = make_float2(oe, oo);
                    }
                } else {
                    float2 bv = *(const float2*)(bias + nc);
                    *(float2*)(out + (size_t)m * C_ + nc) =
                        make_float2(e + bv.x, o + bv.y);
                }
            }
        }
    }
}

// ---------------- fp32 flash attention (unchanged, proven) ------------------
#define AS_ 65
#define ATTN_SMEM (4 * 64 * AS_ * (int)sizeof(float))

__global__ __launch_bounds__(256) void attn_kernel() {
    extern __shared__ float smf[];
    float* Qs = smf;
    float* Ks = smf + 64 * AS_;
    float* Vs = smf + 2 * 64 * AS_;
    float* Ps = smf + 3 * 64 * AS_;

    const int tid = threadIdx.x;
    const int tx = tid & 15, ty = tid >> 4;
    const int qi = (int)gridDim.x - 1 - (int)blockIdx.x;   // heavy-first
    const int bh = blockIdx.y;
    const int b  = bh >> 4;
    const int h  = bh & 15;

    const float* Qg = g_q + ((size_t)bh * T_ + qi * 64) * D_;
    for (int idx = tid; idx < 64 * 64; idx += 256) {
        int r = idx >> 6, d = idx & 63;
        Qs[r * AS_ + d] = Qg[idx];
    }

    float o[4][4] = {};
    float mrow[4], lrow[4];
    #pragma unroll
    for (int i = 0; i < 4; i++) { mrow[i] = -1e30f; lrow[i] = 0.0f; }
    __syncthreads();

    for (int j = 0; j <= qi; j++) {
        const float* Kg = g_k + ((size_t)bh * T_ + j * 64) * D_;
        const float* Vg = g_v + ((size_t)bh * T_ + j * 64) * D_;
        for (int idx = tid; idx < 64 * 64; idx += 256) {
            int r = idx >> 6, d = idx & 63;
            Ks[r * AS_ + d] = Kg[idx];
            Vs[r * AS_ + d] = Vg[idx];
        }
        __syncthreads();

        float s[4][4] = {};
        #pragma unroll 8
        for (int d = 0; d < 64; d++) {
            float a[4], bb[4];
            #pragma unroll
            for (int i = 0; i < 4; i++) a[i]  = Qs[(ty * 4 + i) * AS_ + d];
            #pragma unroll
            for (int c = 0; c < 4; c++) bb[c] = Ks[(tx * 4 + c) * AS_ + d];
            #pragma unroll
            for (int i = 0; i < 4; i++)
                #pragma unroll
                for (int c = 0; c < 4; c++)
                    s[i][c] = fmaf(a[i], bb[c], s[i][c]);
        }

        if (j == qi) {
            #pragma unroll
            for (int i = 0; i < 4; i++)
                #pragma unroll
                for (int c = 0; c < 4; c++)
                    if (tx * 4 + c > ty * 4 + i) s[i][c] = -1e30f;
        }

        #pragma unroll
        for (int i = 0; i < 4; i++) {
            float mx = fmaxf(fmaxf(s[i][0], s[i][1]), fmaxf(s[i][2], s[i][3]));
            #pragma unroll
            for (int off = 8; off > 0; off >>= 1)
                mx = fmaxf(mx, __shfl_xor_sync(0xffffffffu, mx, off));
            float mnew = fmaxf(mrow[i], mx);
            float psum = 0.0f, p[4];
            #pragma unroll
            for (int c = 0; c < 4; c++) { p[c] = __expf(s[i][c] - mnew); psum += p[c]; }
            #pragma unroll
            for (int off = 8; off > 0; off >>= 1)
                psum += __shfl_xor_sync(0xffffffffu, psum, off);
            float fac = __expf(mrow[i] - mnew);
            lrow[i] = lrow[i] * fac + psum;
            mrow[i] = mnew;
            #pragma unroll
            for (int c = 0; c < 4; c++) o[i][c] *= fac;
            #pragma unroll
            for (int c = 0; c < 4; c++) Ps[(ty * 4 + i) * AS_ + tx * 4 + c] = p[c];
        }
        __syncthreads();

        #pragma unroll 8
        for (int kk = 0; kk < 64; kk++) {
            float a[4], bb[4];
            #pragma unroll
            for (int i = 0; i < 4; i++) a[i]  = Ps[(ty * 4 + i) * AS_ + kk];
            #pragma unroll
            for (int c = 0; c < 4; c++) bb[c] = Vs[kk * AS_ + tx * 4 + c];
            #pragma unroll
            for (int i = 0; i < 4; i++)
                #pragma unroll
                for (int c = 0; c < 4; c++)
                    o[i][c] = fmaf(a[i], bb[c], o[i][c]);
        }
        __syncthreads();
    }

    // write y in [B, T, C] layout (feeds proj GEMM)
    #pragma unroll
    for (int i = 0; i < 4; i++) {
        int t = qi * 64 + ty * 4 + i;
        float inv_l = 1.0f / lrow[i];
        #pragma unroll
        for (int c = 0; c < 4; c++)
            g_y[((size_t)(b * T_ + t)) * C_ + h * D_ + tx * 4 + c] = o[i][c] * inv_l;
    }
}

// ---------------------------------------------------------------------------
extern "C" void kernel_launch(void* const* d_in, const int* in_sizes, int n_in,
                              void* d_out, int out_size)
{
    const float* x      = (const float*)d_in[0];
    const float* w_qkv  = (const float*)d_in[1];
    const float* w_proj = (const float*)d_in[2];
    const float* b_proj = (const float*)d_in[3];
    float* out = (float*)d_out;
    (void)in_sizes; (void)n_in; (void)out_size;

    cudaFuncSetAttribute(gemm_tf32<0>,
                         cudaFuncAttributeMaxDynamicSharedMemorySize, GEMM_SMEM_BYTES);
    cudaFuncSetAttribute(gemm_tf32<1>,
                         cudaFuncAttributeMaxDynamicSharedMemorySize, GEMM_SMEM_BYTES);
    cudaFuncSetAttribute(attn_kernel,
                         cudaFuncAttributeMaxDynamicSharedMemorySize, ATTN_SMEM);

    rope_table_kernel<<<256, 256>>>();
    gemm_tf32<0><<<dim3(N3_ / 128, M_ / 128), 256, GEMM_SMEM_BYTES>>>(x, w_qkv, nullptr, nullptr);
    attn_kernel<<<dim3(T_ / 64, BH_), 256, ATTN_SMEM>>>();
    gemm_tf32<1><<<dim3(C_ / 128, M_ / 128), 256, GEMM_SMEM_BYTES>>>(nullptr, w_proj, b_proj, out);
}

// round 6
// speedup vs baseline: 1.1888x; 1.1888x over previous
#include <cuda_runtime.h>
#include <math.h>
#include <stdint.h>

#define B_  2
#define T_  2048
#define C_  1024
#define H_  16
#define D_  64
#define BH_ 32
#define M_  4096
#define N3_ 3072
#define K_  1024

// ---------------- scratch (__device__ globals; no allocs allowed) -----------
// q/k split tf32 hi/lo in [bh][d][t] (k-major for MMA frags);
// v split tf32 hi/lo in [bh][t][d].
__device__ uint32_t g_qh[BH_*D_*T_], g_ql[BH_*D_*T_];
__device__ uint32_t g_kh[BH_*D_*T_], g_kl[BH_*D_*T_];
__device__ uint32_t g_vh[BH_*T_*D_], g_vl[BH_*T_*D_];
__device__ float g_y[M_*C_];
__device__ float g_cos[T_*32], g_sin[T_*32];

// ---------------- helpers ----------------------------------------------------
__device__ __forceinline__ uint32_t smem_u32(const void* p) {
    uint32_t a;
    asm("{ .reg .u64 t; cvta.to.shared.u64 t, %1; cvt.u32.u64 %0, t; }"
        : "=r"(a) : "l"(p));
    return a;
}

__device__ __forceinline__ uint32_t f2tf32(float f) {
    uint32_t u;
    asm("cvt.rna.tf32.f32 %0, %1;" : "=r"(u) : "f"(f));
    return u;
}

__device__ __forceinline__ void mma_tf32(float c[4], const uint32_t a[4],
                                         const uint32_t b[2]) {
    asm volatile(
        "mma.sync.aligned.m16n8k8.row.col.f32.tf32.tf32.f32 "
        "{%0,%1,%2,%3}, {%4,%5,%6,%7}, {%8,%9}, {%0,%1,%2,%3};"
        : "+f"(c[0]), "+f"(c[1]), "+f"(c[2]), "+f"(c[3])
        : "r"(a[0]), "r"(a[1]), "r"(a[2]), "r"(a[3]), "r"(b[0]), "r"(b[1]));
}

// fast exp2 on FMA/ALU pipes (no MUFU). t <= ~+1, clamped below at -126.
__device__ __forceinline__ float fexp2(float t) {
    t = fmaxf(t, -126.0f);
    float r = t + 12582912.0f;              // round-to-nearest-int trick
    int   n = __float_as_int(r);            // low bits hold round(t)+bias
    float f = t - (r - 12582912.0f);        // f in [-0.5, 0.5], exact
    float p = 1.33335581e-3f;
    p = fmaf(p, f, 9.61812911e-3f);
    p = fmaf(p, f, 5.55041087e-2f);
    p = fmaf(p, f, 2.40226507e-1f);
    p = fmaf(p, f, 6.93147180e-1f);
    p = fmaf(p, f, 1.0f);
    return __int_as_float(__float_as_int(p) + (n << 23));
}
#define L2E_ 1.4426950408889634f

__device__ __forceinline__ void cpa16(uint32_t s, const void* gp) {
    asm volatile("cp.async.cg.shared.global [%0], [%1], 16;" :: "r"(s), "l"(gp));
}
#define CP_COMMIT() asm volatile("cp.async.commit_group;" ::: "memory")
#define CP_WAIT0()  asm volatile("cp.async.wait_group 0;" ::: "memory")

// ---------------- RoPE table -------------------------------------------------
__global__ void rope_table_kernel() {
    int idx = blockIdx.x * 256 + threadIdx.x;   // 65536 = 2048*32
    int t = idx >> 5, i = idx & 31;
    double inv = pow(10000.0, -(double)(2 * i) / 64.0);
    float ff = (float)t * (float)inv;
    double s, c;
    sincos((double)ff, &s, &c);
    g_cos[idx] = (float)c;
    g_sin[idx] = (float)s;
}

// ---------------- 3-pass split-tf32 warp-MMA GEMM ----------------------------
#define SST 136
#define TILE_W   (32 * SST)
#define GEMM_SMEM_BYTES (4 * TILE_W * 4)        // 69,632 B

__device__ __forceinline__ void split_store(uint32_t* hi, uint32_t* lo,
                                            size_t idx, float v) {
    uint32_t h = f2tf32(v);
    hi[idx] = h;
    lo[idx] = f2tf32(v - __uint_as_float(h));
}

template <int MODE>
__global__ __launch_bounds__(256, 2) void gemm_tf32(
    const float* __restrict__ Ain, const float* __restrict__ W,
    const float* __restrict__ bias, float* __restrict__ out)
{
    const int N = MODE ? C_ : N3_;
    extern __shared__ uint32_t dsm[];
    uint32_t (*Ah)[SST] = (uint32_t(*)[SST])(dsm);
    uint32_t (*Al)[SST] = (uint32_t(*)[SST])(dsm + TILE_W);
    uint32_t (*Bh)[SST] = (uint32_t(*)[SST])(dsm + 2 * TILE_W);
    uint32_t (*Bl)[SST] = (uint32_t(*)[SST])(dsm + 3 * TILE_W);

    // device-side symbol (host-side g_y would be the host shadow address)
    const float* A = MODE ? (const float*)g_y : Ain;

    const int tid  = threadIdx.x;
    const int wid  = tid >> 5;
    const int lane = tid & 31;
    const int g  = lane >> 2;
    const int tq = lane & 3;
    const int wm = wid >> 2;
    const int wn = wid & 3;
    const int m0 = blockIdx.y * 128;
    const int n0 = blockIdx.x * 128;

    float acc[4][4][4] = {};

    for (int kk = 0; kk < K_; kk += 32) {
        #pragma unroll
        for (int i = 0; i < 4; i++) {
            int q = i * 256 + tid;
            int m = q >> 3, j = (q & 7) << 2;
            float4 v = *(const float4*)(A + (size_t)(m0 + m) * K_ + kk + j);
            float vv[4] = {v.x, v.y, v.z, v.w};
            #pragma unroll
            for (int c = 0; c < 4; c++) {
                uint32_t h = f2tf32(vv[c]);
                Ah[j + c][m] = h;
                Al[j + c][m] = f2tf32(vv[c] - __uint_as_float(h));
            }
        }
        #pragma unroll
        for (int i = 0; i < 4; i++) {
            int q = i * 256 + tid;
            int k = q >> 5, j = (q & 31) << 2;
            float4 v = *(const float4*)(W + (size_t)(kk + k) * N + n0 + j);
            uint4 uh, ul;
            uh.x = f2tf32(v.x); ul.x = f2tf32(v.x - __uint_as_float(uh.x));
            uh.y = f2tf32(v.y); ul.y = f2tf32(v.y - __uint_as_float(uh.y));
            uh.z = f2tf32(v.z); ul.z = f2tf32(v.z - __uint_as_float(uh.z));
            uh.w = f2tf32(v.w); ul.w = f2tf32(v.w - __uint_as_float(uh.w));
            *(uint4*)&Bh[k][j] = uh;
            *(uint4*)&Bl[k][j] = ul;
        }
        __syncthreads();

        #pragma unroll
        for (int k8 = 0; k8 < 4; k8++) {
            const int k0 = k8 * 8;
            uint32_t ah[4][4], al[4][4], bh[4][2], bl[4][2];
            #pragma unroll
            for (int mi = 0; mi < 4; mi++) {
                int mb = wm * 64 + mi * 16 + g;
                ah[mi][0] = Ah[k0 + tq][mb];
                ah[mi][1] = Ah[k0 + tq][mb + 8];
                ah[mi][2] = Ah[k0 + tq + 4][mb];
                ah[mi][3] = Ah[k0 + tq + 4][mb + 8];
                al[mi][0] = Al[k0 + tq][mb];
                al[mi][1] = Al[k0 + tq][mb + 8];
                al[mi][2] = Al[k0 + tq + 4][mb];
                al[mi][3] = Al[k0 + tq + 4][mb + 8];
            }
            #pragma unroll
            for (int ni = 0; ni < 4; ni++) {
                int nb = wn * 32 + ni * 8 + g;
                bh[ni][0] = Bh[k0 + tq][nb];
                bh[ni][1] = Bh[k0 + tq + 4][nb];
                bl[ni][0] = Bl[k0 + tq][nb];
                bl[ni][1] = Bl[k0 + tq + 4][nb];
            }
            #pragma unroll
            for (int mi = 0; mi < 4; mi++)
                #pragma unroll
                for (int ni = 0; ni < 4; ni++) {
                    mma_tf32(acc[mi][ni], ah[mi], bh[ni]);
                    mma_tf32(acc[mi][ni], al[mi], bh[ni]);
                    mma_tf32(acc[mi][ni], ah[mi], bl[ni]);
                }
        }
        __syncthreads();
    }

    // ------------- epilogue -------------
    #pragma unroll
    for (int mi = 0; mi < 4; mi++) {
        #pragma unroll
        for (int ni = 0; ni < 4; ni++) {
            const float* c = acc[mi][ni];
            int r0 = m0 + wm * 64 + mi * 16 + g;
            int nc = n0 + wn * 32 + ni * 8 + 2 * tq;
            #pragma unroll
            for (int half = 0; half < 2; half++) {
                int m = r0 + half * 8;
                float e = c[half * 2 + 0];
                float o = c[half * 2 + 1];
                if (MODE == 0) {
                    int b = m >> 11, t = m & 2047;
                    int sec = nc >> 10, cc = nc & 1023;
                    int hd = cc >> 6, d = cc & 63;       // d even
                    if (sec == 2) {
                        size_t vb = ((size_t)((b << 4) + hd) * T_ + t) * D_ + d;
                        uint32_t he = f2tf32(e), ho = f2tf32(o);
                        *(uint2*)&g_vh[vb] = make_uint2(he, ho);
                        *(uint2*)&g_vl[vb] = make_uint2(
                            f2tf32(e - __uint_as_float(he)),
                            f2tf32(o - __uint_as_float(ho)));
                    } else {
                        float co = g_cos[t * 32 + (d >> 1)];
                        float si = g_sin[t * 32 + (d >> 1)];
                        float oe = e * co - o * si;
                        float oo = e * si + o * co;
                        size_t base = ((size_t)((b << 4) + hd) * D_ + d) * T_ + t;
                        if (sec == 0) {
                            split_store(g_qh, g_ql, base,        oe * 0.125f);
                            split_store(g_qh, g_ql, base + T_,   oo * 0.125f);
                        } else {
                            split_store(g_kh, g_kl, base,        oe);
                            split_store(g_kh, g_kl, base + T_,   oo);
                        }
                    }
                } else {
                    float2 bv = *(const float2*)(bias + nc);
                    *(float2*)(out + (size_t)m * C_ + nc) =
                        make_float2(e + bv.x, o + bv.y);
                }
            }
        }
    }
}

// ---------------- MMA flash attention (split-tf32, 3-pass) ------------------
// CTA: 128 q-rows x 64 kv per tile step. 8 warps, each owns m16 (q rows
// w*16..w*16+15). All operands pre-split tf32 in global; cp.async straight in.
#define QSTR 132
#define KSTR 68
#define OFF_QH 0
#define OFF_QL (OFF_QH + 64*QSTR)
#define OFF_KH (OFF_QL + 64*QSTR)
#define OFF_KL (OFF_KH + 64*KSTR)
#define OFF_VH (OFF_KL + 64*KSTR)
#define OFF_VL (OFF_VH + 64*KSTR)
#define OFF_PS (OFF_VL + 64*KSTR)
#define ATTN_WORDS (OFF_PS + 64*QSTR)
#define ATTN_SMEM_B (ATTN_WORDS * 4)    // 171,008 B

__global__ __launch_bounds__(256) void attn_mma() {
    extern __shared__ uint32_t sw[];
    const uint32_t sb = smem_u32(sw);
    const int tid  = threadIdx.x;
    const int wid  = tid >> 5, lane = tid & 31;
    const int g    = lane >> 2, tq = lane & 3;
    const int qt   = (int)gridDim.x - 1 - (int)blockIdx.x;  // heavy-first
    const int bh   = blockIdx.y;
    const int q0   = qt * 128;

    const uint32_t* gqh = g_qh + (size_t)bh * D_ * T_;
    const uint32_t* gql = g_ql + (size_t)bh * D_ * T_;
    const uint32_t* gkh = g_kh + (size_t)bh * D_ * T_;
    const uint32_t* gkl = g_kl + (size_t)bh * D_ * T_;
    const uint32_t* gvh = g_vh + (size_t)bh * T_ * D_;
    const uint32_t* gvl = g_vl + (size_t)bh * T_ * D_;

    // Q tiles: 64 d-rows x 128 t, straight copy (already [d][t] split tf32)
    #pragma unroll
    for (int c = tid; c < 64 * 32; c += 256) {
        int d = c >> 5, ch = (c & 31) << 2;
        cpa16(sb + (OFF_QH + d * QSTR + ch) * 4, gqh + (size_t)d * T_ + q0 + ch);
        cpa16(sb + (OFF_QL + d * QSTR + ch) * 4, gql + (size_t)d * T_ + q0 + ch);
    }
    CP_COMMIT();

    float accO[8][4] = {};
    float mrow[2] = {-1e30f, -1e30f};
    float lrow[2] = {0.0f, 0.0f};

    const int nkv = 2 * qt + 2;
    const int wrow0 = q0 + wid * 16;      // this warp's first q row

    for (int j = 0; j < nkv; j++) {
        const int kv0 = j * 64;
        // load K (d-major) and V (t-major) tiles, split hi/lo
        #pragma unroll
        for (int c = tid; c < 1024; c += 256) {
            int r = c >> 4, ch = (c & 15) << 2;
            cpa16(sb + (OFF_KH + r * KSTR + ch) * 4, gkh + (size_t)r * T_ + kv0 + ch);
            cpa16(sb + (OFF_KL + r * KSTR + ch) * 4, gkl + (size_t)r * T_ + kv0 + ch);
            cpa16(sb + (OFF_VH + r * KSTR + ch) * 4, gvh + (size_t)(kv0 + r) * D_ + ch);
            cpa16(sb + (OFF_VL + r * KSTR + ch) * 4, gvl + (size_t)(kv0 + r) * D_ + ch);
        }
        CP_COMMIT();
        CP_WAIT0();
        __syncthreads();

        if (kv0 <= wrow0 + 15) {          // warp has unmasked rows in tile
            // ---- S = Q @ K^T (3-pass split tf32) ----
            float accS[8][4] = {};
            #pragma unroll
            for (int ks = 0; ks < 8; ks++) {
                const int k0 = ks * 8;
                uint32_t qh[4], ql[4];
                const int mb = wid * 16 + g;
                qh[0] = sw[OFF_QH + (k0 + tq) * QSTR + mb];
                qh[1] = sw[OFF_QH + (k0 + tq) * QSTR + mb + 8];
                qh[2] = sw[OFF_QH + (k0 + tq + 4) * QSTR + mb];
                qh[3] = sw[OFF_QH + (k0 + tq + 4) * QSTR + mb + 8];
                ql[0] = sw[OFF_QL + (k0 + tq) * QSTR + mb];
                ql[1] = sw[OFF_QL + (k0 + tq) * QSTR + mb + 8];
                ql[2] = sw[OFF_QL + (k0 + tq + 4) * QSTR + mb];
                ql[3] = sw[OFF_QL + (k0 + tq + 4) * QSTR + mb + 8];
                #pragma unroll
                for (int nf = 0; nf < 8; nf++) {
                    uint32_t kh[2], kl[2];
                    const int nb = nf * 8 + g;
                    kh[0] = sw[OFF_KH + (k0 + tq) * KSTR + nb];
                    kh[1] = sw[OFF_KH + (k0 + tq + 4) * KSTR + nb];
                    kl[0] = sw[OFF_KL + (k0 + tq) * KSTR + nb];
                    kl[1] = sw[OFF_KL + (k0 + tq + 4) * KSTR + nb];
                    mma_tf32(accS[nf], qh, kh);
                    mma_tf32(accS[nf], ql, kh);
                    mma_tf32(accS[nf], qh, kl);
                }
            }

            // ---- causal mask (only tiles near the diagonal) ----
            if (kv0 + 63 > wrow0) {
                #pragma unroll
                for (int nf = 0; nf < 8; nf++)
                    #pragma unroll
                    for (int r = 0; r < 4; r++) {
                        int row = wrow0 + g + (r >> 1) * 8;
                        int col = kv0 + nf * 8 + 2 * tq + (r & 1);
                        if (col > row) accS[nf][r] = -1e30f;
                    }
            }

            // ---- online softmax (polynomial exp2, no MUFU) ----
            #pragma unroll
            for (int hh = 0; hh < 2; hh++) {
                float mx = -1e30f;
                #pragma unroll
                for (int nf = 0; nf < 8; nf++)
                    mx = fmaxf(mx, fmaxf(accS[nf][2*hh], accS[nf][2*hh+1]));
                mx = fmaxf(mx, __shfl_xor_sync(0xffffffffu, mx, 1));
                mx = fmaxf(mx, __shfl_xor_sync(0xffffffffu, mx, 2));
                float mn = fmaxf(mrow[hh], mx);
                float corr = fexp2((mrow[hh] - mn) * L2E_);
                mrow[hh] = mn;
                float mnL = mn * L2E_;
                float ps = 0.0f;
                #pragma unroll
                for (int nf = 0; nf < 8; nf++) {
                    float p0 = fexp2(fmaf(accS[nf][2*hh],   L2E_, -mnL));
                    float p1 = fexp2(fmaf(accS[nf][2*hh+1], L2E_, -mnL));
                    accS[nf][2*hh] = p0; accS[nf][2*hh+1] = p1;
                    ps += p0 + p1;
                }
                ps += __shfl_xor_sync(0xffffffffu, ps, 1);
                ps += __shfl_xor_sync(0xffffffffu, ps, 2);
                lrow[hh] = lrow[hh] * corr + ps;
                #pragma unroll
                for (int nf = 0; nf < 8; nf++) {
                    accO[nf][2*hh]   *= corr;
                    accO[nf][2*hh+1] *= corr;
                }
            }

            // ---- store P (fp32) to smem [kv][m]; per-warp region disjoint ----
            #pragma unroll
            for (int nf = 0; nf < 8; nf++)
                #pragma unroll
                for (int r = 0; r < 4; r++) {
                    int col = nf * 8 + 2 * tq + (r & 1);
                    int row = wid * 16 + g + (r >> 1) * 8;
                    sw[OFF_PS + col * QSTR + row] = __float_as_uint(accS[nf][r]);
                }
            __syncwarp();

            // ---- O += P @ V (3-pass: ph*vh + pl*vh + ph*vl) ----
            #pragma unroll
            for (int ks = 0; ks < 8; ks++) {
                const int k0 = ks * 8;
                const int mb = wid * 16 + g;
                float pa[4];
                pa[0] = __uint_as_float(sw[OFF_PS + (k0 + tq) * QSTR + mb]);
                pa[1] = __uint_as_float(sw[OFF_PS + (k0 + tq) * QSTR + mb + 8]);
                pa[2] = __uint_as_float(sw[OFF_PS + (k0 + tq + 4) * QSTR + mb]);
                pa[3] = __uint_as_float(sw[OFF_PS + (k0 + tq + 4) * QSTR + mb + 8]);
                uint32_t ph[4], pl[4];
                #pragma unroll
                for (int r = 0; r < 4; r++) {
                    ph[r] = f2tf32(pa[r]);
                    pl[r] = f2tf32(pa[r] - __uint_as_float(ph[r]));
                }
                #pragma unroll
                for (int nf = 0; nf < 8; nf++) {
                    uint32_t vh[2], vl[2];
                    const int nb = nf * 8 + g;
                    vh[0] = sw[OFF_VH + (k0 + tq) * KSTR + nb];
                    vh[1] = sw[OFF_VH + (k0 + tq + 4) * KSTR + nb];
                    vl[0] = sw[OFF_VL + (k0 + tq) * KSTR + nb];
                    vl[1] = sw[OFF_VL + (k0 + tq + 4) * KSTR + nb];
                    mma_tf32(accO[nf], ph, vh);
                    mma_tf32(accO[nf], pl, vh);
                    mma_tf32(accO[nf], ph, vl);
                }
            }
        }
        __syncthreads();   // protect K/V/P smem before next tile's cp.async
    }

    // ---- write y [B,T,C] ----
    const int b = bh >> 4, hd = bh & 15;
    #pragma unroll
    for (int hh = 0; hh < 2; hh++) {
        float inv = 1.0f / lrow[hh];
        int t = q0 + wid * 16 + g + hh * 8;
        float* yrow = g_y + (size_t)(b * T_ + t) * C_ + hd * 64;
        #pragma unroll
        for (int nf = 0; nf < 8; nf++)
            *(float2*)(yrow + nf * 8 + 2 * tq) =
                make_float2(accO[nf][2*hh] * inv, accO[nf][2*hh+1] * inv);
    }
}

// ---------------------------------------------------------------------------
extern "C" void kernel_launch(void* const* d_in, const int* in_sizes, int n_in,
                              void* d_out, int out_size)
{
    const float* x      = (const float*)d_in[0];
    const float* w_qkv  = (const float*)d_in[1];
    const float* w_proj = (const float*)d_in[2];
    const float* b_proj = (const float*)d_in[3];
    float* out = (float*)d_out;
    (void)in_sizes; (void)n_in; (void)out_size;

    cudaFuncSetAttribute(gemm_tf32<0>,
                         cudaFuncAttributeMaxDynamicSharedMemorySize, GEMM_SMEM_BYTES);
    cudaFuncSetAttribute(gemm_tf32<1>,
                         cudaFuncAttributeMaxDynamicSharedMemorySize, GEMM_SMEM_BYTES);
    cudaFuncSetAttribute(attn_mma,
                         cudaFuncAttributeMaxDynamicSharedMemorySize, ATTN_SMEM_B);

    rope_table_kernel<<<256, 256>>>();
    gemm_tf32<0><<<dim3(N3_ / 128, M_ / 128), 256, GEMM_SMEM_BYTES>>>(x, w_qkv, nullptr, nullptr);
    attn_mma<<<dim3(T_ / 128, BH_), 256, ATTN_SMEM_B>>>();
    gemm_tf32<1><<<dim3(C_ / 128, M_ / 128), 256, GEMM_SMEM_BYTES>>>(nullptr, w_proj, b_proj, out);
}

// round 7
// speedup vs baseline: 1.3513x; 1.1368x over previous
#include <cuda_runtime.h>
#include <math.h>
#include <stdint.h>

#define B_  2
#define T_  2048
#define C_  1024
#define H_  16
#define D_  64
#define BH_ 32
#define M_  4096
#define N3_ 3072
#define K_  1024

// ---------------- scratch (__device__ globals; no allocs allowed) -----------
// q/k raw fp32 in [bh][d][t] (k-major for S-mma frags); v raw fp32 [bh][t][d].
__device__ float g_q[BH_*D_*T_];
__device__ float g_k[BH_*D_*T_];
__device__ float g_v[BH_*T_*D_];
__device__ float g_y[M_*C_];
__device__ float g_cos[T_*32], g_sin[T_*32];

// ---------------- helpers ----------------------------------------------------
__device__ __forceinline__ uint32_t smem_u32(const void* p) {
    uint32_t a;
    asm("{ .reg .u64 t; cvta.to.shared.u64 t, %1; cvt.u32.u64 %0, t; }"
        : "=r"(a) : "l"(p));
    return a;
}

__device__ __forceinline__ uint32_t f2tf32(float f) {
    uint32_t u;
    asm("cvt.rna.tf32.f32 %0, %1;" : "=r"(u) : "f"(f));
    return u;
}

// split one raw float into tf32 hi/lo
__device__ __forceinline__ void split2(float r, uint32_t& h, uint32_t& l) {
    h = f2tf32(r);
    l = f2tf32(r - __uint_as_float(h));
}

__device__ __forceinline__ void mma_tf32(float c[4], const uint32_t a[4],
                                         const uint32_t b[2]) {
    asm volatile(
        "mma.sync.aligned.m16n8k8.row.col.f32.tf32.tf32.f32 "
        "{%0,%1,%2,%3}, {%4,%5,%6,%7}, {%8,%9}, {%0,%1,%2,%3};"
        : "+f"(c[0]), "+f"(c[1]), "+f"(c[2]), "+f"(c[3])
        : "r"(a[0]), "r"(a[1]), "r"(a[2]), "r"(a[3]), "r"(b[0]), "r"(b[1]));
}

// fast exp2 on FMA/ALU pipes (no MUFU)
__device__ __forceinline__ float fexp2(float t) {
    t = fmaxf(t, -126.0f);
    float r = t + 12582912.0f;
    int   n = __float_as_int(r);
    float f = t - (r - 12582912.0f);
    float p = 1.33335581e-3f;
    p = fmaf(p, f, 9.61812911e-3f);
    p = fmaf(p, f, 5.55041087e-2f);
    p = fmaf(p, f, 2.40226507e-1f);
    p = fmaf(p, f, 6.93147180e-1f);
    p = fmaf(p, f, 1.0f);
    return __int_as_float(__float_as_int(p) + (n << 23));
}
#define L2E_ 1.4426950408889634f

__device__ __forceinline__ void cpa16(uint32_t s, const void* gp) {
    asm volatile("cp.async.cg.shared.global [%0], [%1], 16;" :: "r"(s), "l"(gp));
}
#define CP_COMMIT() asm volatile("cp.async.commit_group;" ::: "memory")
#define CP_WAIT1()  asm volatile("cp.async.wait_group 1;" ::: "memory")

// ---------------- RoPE table -------------------------------------------------
__global__ void rope_table_kernel() {
    int idx = blockIdx.x * 256 + threadIdx.x;   // 65536
    int t = idx >> 5, i = idx & 31;
    double inv = pow(10000.0, -(double)(2 * i) / 64.0);
    float ff = (float)t * (float)inv;
    double s, c;
    sincos((double)ff, &s, &c);
    g_cos[idx] = (float)c;
    g_sin[idx] = (float)s;
}

// ---------------- split-tf32 GEMM, raw-fp32 smem, cp.async double buffer ----
#define ASTR 36                       // A smem row stride (4g+tq banks)
#define AS_W (128 * ASTR)             // 4608 words
#define BSTR 136                      // B smem row stride (8tq+g banks)
#define BS_W (32 * BSTR)              // 4352 words
#define STG_W (AS_W + BS_W)           // 8960 words / stage
#define GEMM_SMEM_BYTES (2 * STG_W * 4)  // 71,680 B

__device__ __forceinline__ void gemm_load_stage(
    uint32_t su, const float* __restrict__ A, const float* __restrict__ W,
    int m0, int n0, int kk, int N, int tid)
{
    const uint32_t bu = su + AS_W * 4;
    #pragma unroll
    for (int i = 0; i < 4; i++) {               // A: 128m x 32k, row-major
        int c = i * 256 + tid;
        int m = c >> 3, ch = c & 7;
        cpa16(su + (m * ASTR + ch * 4) * 4, A + (size_t)(m0 + m) * K_ + kk + ch * 4);
    }
    #pragma unroll
    for (int i = 0; i < 4; i++) {               // B: 32k x 128n, row-major
        int c = i * 256 + tid;
        int k = c >> 5, ch = c & 31;
        cpa16(bu + (k * BSTR + ch * 4) * 4, W + (size_t)(kk + k) * N + n0 + ch * 4);
    }
}

template <int MODE>
__global__ __launch_bounds__(256, 2) void gemm_tf32(
    const float* __restrict__ Ain, const float* __restrict__ W,
    const float* __restrict__ bias, float* __restrict__ out)
{
    const int N = MODE ? C_ : N3_;
    extern __shared__ float dsm[];
    const uint32_t sb = smem_u32(dsm);

    // device-side symbol (host-side g_y would be the host shadow address)
    const float* A = MODE ? (const float*)g_y : Ain;

    const int tid  = threadIdx.x;
    const int wid  = tid >> 5;
    const int lane = tid & 31;
    const int g  = lane >> 2;
    const int tq = lane & 3;
    const int wm = wid >> 2;
    const int wn = wid & 3;
    const int m0 = blockIdx.y * 128;
    const int n0 = blockIdx.x * 128;

    float acc[4][4][4] = {};

    gemm_load_stage(sb, A, W, m0, n0, 0, N, tid);
    CP_COMMIT();

    for (int kk = 0; kk < K_; kk += 32) {
        const int s = (kk >> 5) & 1;
        if (kk + 32 < K_)
            gemm_load_stage(sb + (uint32_t)(s ^ 1) * STG_W * 4, A, W, m0, n0,
                            kk + 32, N, tid);
        CP_COMMIT();
        CP_WAIT1();
        __syncthreads();

        const float* As = dsm + s * STG_W;
        const float* Bs = As + AS_W;

        #pragma unroll
        for (int k8 = 0; k8 < 4; k8++) {
            const int k0 = k8 * 8;
            uint32_t ah[4][4], al[4][4], bh[4][2], bl[4][2];
            #pragma unroll
            for (int mi = 0; mi < 4; mi++) {
                int mb = wm * 64 + mi * 16 + g;
                split2(As[(size_t)mb * ASTR + k0 + tq],            ah[mi][0], al[mi][0]);
                split2(As[(size_t)(mb + 8) * ASTR + k0 + tq],      ah[mi][1], al[mi][1]);
                split2(As[(size_t)mb * ASTR + k0 + tq + 4],        ah[mi][2], al[mi][2]);
                split2(As[(size_t)(mb + 8) * ASTR + k0 + tq + 4],  ah[mi][3], al[mi][3]);
            }
            #pragma unroll
            for (int ni = 0; ni < 4; ni++) {
                int nb = wn * 32 + ni * 8 + g;
                split2(Bs[(size_t)(k0 + tq) * BSTR + nb],       bh[ni][0], bl[ni][0]);
                split2(Bs[(size_t)(k0 + tq + 4) * BSTR + nb],   bh[ni][1], bl[ni][1]);
            }
            #pragma unroll
            for (int mi = 0; mi < 4; mi++)
                #pragma unroll
                for (int ni = 0; ni < 4; ni++) {
                    mma_tf32(acc[mi][ni], ah[mi], bh[ni]);
                    mma_tf32(acc[mi][ni], al[mi], bh[ni]);
                    mma_tf32(acc[mi][ni], ah[mi], bl[ni]);
                }
        }
        __syncthreads();
    }

    // ------------- epilogue -------------
    #pragma unroll
    for (int mi = 0; mi < 4; mi++) {
        #pragma unroll
        for (int ni = 0; ni < 4; ni++) {
            const float* c = acc[mi][ni];
            int r0 = m0 + wm * 64 + mi * 16 + g;
            int nc = n0 + wn * 32 + ni * 8 + 2 * tq;
            #pragma unroll
            for (int half = 0; half < 2; half++) {
                int m = r0 + half * 8;
                float e = c[half * 2 + 0];
                float o = c[half * 2 + 1];
                if (MODE == 0) {
                    int b = m >> 11, t = m & 2047;
                    int sec = nc >> 10, cc = nc & 1023;
                    int hd = cc >> 6, d = cc & 63;       // d even
                    if (sec == 2) {
                        size_t vb = ((size_t)((b << 4) + hd) * T_ + t) * D_ + d;
                        *(float2*)(g_v + vb) = make_float2(e, o);
                    } else {
                        float co = g_cos[t * 32 + (d >> 1)];
                        float si = g_sin[t * 32 + (d >> 1)];
                        float oe = e * co - o * si;
                        float oo = e * si + o * co;
                        size_t base = ((size_t)((b << 4) + hd) * D_ + d) * T_ + t;
                        if (sec == 0) {
                            g_q[base]      = oe * 0.125f;
                            g_q[base + T_] = oo * 0.125f;
                        } else {
                            g_k[base]      = oe;
                            g_k[base + T_] = oo;
                        }
                    }
                } else {
                    float2 bv = *(const float2*)(bias + nc);
                    *(float2*)(out + (size_t)m * C_ + nc) =
                        make_float2(e + bv.x, o + bv.y);
                }
            }
        }
    }
}

// ---------------- MMA flash attention v2 -------------------------------------
// 128 q x 64 kv per step; 8 warps each own m16. Q frags converted ONCE into
// registers. K/V raw fp32 in smem, double-buffered cp.async; split at frag load.
#define KSTR 68
#define KV_W (64 * KSTR)                  // one K or V tile, words
#define KVSTG_W (2 * KV_W)                // K+V per stage
#define OFF_PS (2 * KVSTG_W)              // after the 2 stages
#define PSTR 132
#define ATTN_WORDS (OFF_PS + 64 * PSTR)
#define ATTN_SMEM_B (ATTN_WORDS * 4)      // 103,424 B

__device__ __forceinline__ void attn_load_kv(
    uint32_t su, const float* __restrict__ gk, const float* __restrict__ gv,
    int kv0, int tid)
{
    const uint32_t vu = su + KV_W * 4;
    #pragma unroll
    for (int i = 0; i < 4; i++) {             // K: [d][t] 64x64
        int c = i * 256 + tid;
        int r = c >> 4, ch = c & 15;
        cpa16(su + (r * KSTR + ch * 4) * 4, gk + (size_t)r * T_ + kv0 + ch * 4);
    }
    #pragma unroll
    for (int i = 0; i < 4; i++) {             // V: [t][d] 64x64
        int c = i * 256 + tid;
        int r = c >> 4, ch = c & 15;
        cpa16(vu + (r * KSTR + ch * 4) * 4, gv + (size_t)(kv0 + r) * D_ + ch * 4);
    }
}

__global__ __launch_bounds__(256) void attn_mma() {
    extern __shared__ float swf[];
    uint32_t* sw = (uint32_t*)swf;
    const uint32_t sb = smem_u32(swf);
    const int tid  = threadIdx.x;
    const int wid  = tid >> 5, lane = tid & 31;
    const int g    = lane >> 2, tq = lane & 3;
    const int qt   = (int)gridDim.x - 1 - (int)blockIdx.x;  // heavy-first
    const int bh   = blockIdx.y;
    const int q0   = qt * 128;

    const float* gq = g_q + (size_t)bh * D_ * T_;
    const float* gk = g_k + (size_t)bh * D_ * T_;
    const float* gv = g_v + (size_t)bh * T_ * D_;

    // ---- Q fragments: load + split once, live in registers ----
    const int mbq = wid * 16 + g;
    uint32_t qh[8][4], ql[8][4];
    #pragma unroll
    for (int ks = 0; ks < 8; ks++) {
        split2(gq[(size_t)(ks * 8 + tq) * T_ + q0 + mbq],         qh[ks][0], ql[ks][0]);
        split2(gq[(size_t)(ks * 8 + tq) * T_ + q0 + mbq + 8],     qh[ks][1], ql[ks][1]);
        split2(gq[(size_t)(ks * 8 + tq + 4) * T_ + q0 + mbq],     qh[ks][2], ql[ks][2]);
        split2(gq[(size_t)(ks * 8 + tq + 4) * T_ + q0 + mbq + 8], qh[ks][3], ql[ks][3]);
    }

    float accO[8][4] = {};
    float mrow[2] = {-1e30f, -1e30f};
    float lrow[2] = {0.0f, 0.0f};

    const int nkv = 2 * qt + 2;
    const int wrow0 = q0 + wid * 16;

    attn_load_kv(sb, gk, gv, 0, tid);
    CP_COMMIT();

    for (int j = 0; j < nkv; j++) {
        const int s = j & 1;
        const int kv0 = j * 64;
        if (j + 1 < nkv)
            attn_load_kv(sb + (uint32_t)(s ^ 1) * KVSTG_W * 4, gk, gv, kv0 + 64, tid);
        CP_COMMIT();
        CP_WAIT1();
        __syncthreads();

        if (kv0 <= wrow0 + 15) {
            const float* Ks = swf + s * KVSTG_W;
            const float* Vs = Ks + KV_W;

            // ---- S = Q @ K^T ----
            float accS[8][4] = {};
            #pragma unroll
            for (int ks = 0; ks < 8; ks++) {
                const int k0 = ks * 8;
                #pragma unroll
                for (int nf = 0; nf < 8; nf++) {
                    const int nb = nf * 8 + g;
                    uint32_t kh[2], kl[2];
                    split2(Ks[(size_t)(k0 + tq) * KSTR + nb],     kh[0], kl[0]);
                    split2(Ks[(size_t)(k0 + tq + 4) * KSTR + nb], kh[1], kl[1]);
                    mma_tf32(accS[nf], qh[ks], kh);
                    mma_tf32(accS[nf], ql[ks], kh);
                    mma_tf32(accS[nf], qh[ks], kl);
                }
            }

            // ---- causal mask ----
            if (kv0 + 63 > wrow0) {
                #pragma unroll
                for (int nf = 0; nf < 8; nf++)
                    #pragma unroll
                    for (int r = 0; r < 4; r++) {
                        int row = wrow0 + g + (r >> 1) * 8;
                        int col = kv0 + nf * 8 + 2 * tq + (r & 1);
                        if (col > row) accS[nf][r] = -1e30f;
                    }
            }

            // ---- online softmax (fexp2, no MUFU) ----
            #pragma unroll
            for (int hh = 0; hh < 2; hh++) {
                float mx = -1e30f;
                #pragma unroll
                for (int nf = 0; nf < 8; nf++)
                    mx = fmaxf(mx, fmaxf(accS[nf][2*hh], accS[nf][2*hh+1]));
                mx = fmaxf(mx, __shfl_xor_sync(0xffffffffu, mx, 1));
                mx = fmaxf(mx, __shfl_xor_sync(0xffffffffu, mx, 2));
                float mn = fmaxf(mrow[hh], mx);
                float corr = fexp2((mrow[hh] - mn) * L2E_);
                mrow[hh] = mn;
                float mnL = mn * L2E_;
                float ps = 0.0f;
                #pragma unroll
                for (int nf = 0; nf < 8; nf++) {
                    float p0 = fexp2(fmaf(accS[nf][2*hh],   L2E_, -mnL));
                    float p1 = fexp2(fmaf(accS[nf][2*hh+1], L2E_, -mnL));
                    accS[nf][2*hh] = p0; accS[nf][2*hh+1] = p1;
                    ps += p0 + p1;
                }
                ps += __shfl_xor_sync(0xffffffffu, ps, 1);
                ps += __shfl_xor_sync(0xffffffffu, ps, 2);
                lrow[hh] = lrow[hh] * corr + ps;
                #pragma unroll
                for (int nf = 0; nf < 8; nf++) {
                    accO[nf][2*hh]   *= corr;
                    accO[nf][2*hh+1] *= corr;
                }
            }

            // ---- P -> smem (per-warp disjoint region) ----
            #pragma unroll
            for (int nf = 0; nf < 8; nf++)
                #pragma unroll
                for (int r = 0; r < 4; r++) {
                    int col = nf * 8 + 2 * tq + (r & 1);
                    int row = wid * 16 + g + (r >> 1) * 8;
                    sw[OFF_PS + col * PSTR + row] = __float_as_uint(accS[nf][r]);
                }
            __syncwarp();

            // ---- O += P @ V ----
            #pragma unroll
            for (int ks = 0; ks < 8; ks++) {
                const int k0 = ks * 8;
                const int mb = wid * 16 + g;
                uint32_t ph[4], pl[4];
                split2(__uint_as_float(sw[OFF_PS + (k0 + tq) * PSTR + mb]),         ph[0], pl[0]);
                split2(__uint_as_float(sw[OFF_PS + (k0 + tq) * PSTR + mb + 8]),     ph[1], pl[1]);
                split2(__uint_as_float(sw[OFF_PS + (k0 + tq + 4) * PSTR + mb]),     ph[2], pl[2]);
                split2(__uint_as_float(sw[OFF_PS + (k0 + tq + 4) * PSTR + mb + 8]), ph[3], pl[3]);
                #pragma unroll
                for (int nf = 0; nf < 8; nf++) {
                    const int nb = nf * 8 + g;
                    uint32_t vh[2], vl[2];
                    split2(Vs[(size_t)(k0 + tq) * KSTR + nb],     vh[0], vl[0]);
                    split2(Vs[(size_t)(k0 + tq + 4) * KSTR + nb], vh[1], vl[1]);
                    mma_tf32(accO[nf], ph, vh);
                    mma_tf32(accO[nf], pl, vh);
                    mma_tf32(accO[nf], ph, vl);
                }
            }
        }
        __syncthreads();
    }

    // ---- write y [B,T,C] ----
    const int b = bh >> 4, hd = bh & 15;
    #pragma unroll
    for (int hh = 0; hh < 2; hh++) {
        float inv = 1.0f / lrow[hh];
        int t = q0 + wid * 16 + g + hh * 8;
        float* yrow = g_y + (size_t)(b * T_ + t) * C_ + hd * 64;
        #pragma unroll
        for (int nf = 0; nf < 8; nf++)
            *(float2*)(yrow + nf * 8 + 2 * tq) =
                make_float2(accO[nf][2*hh] * inv, accO[nf][2*hh+1] * inv);
    }
}

// ---------------------------------------------------------------------------
extern "C" void kernel_launch(void* const* d_in, const int* in_sizes, int n_in,
                              void* d_out, int out_size)
{
    const float* x      = (const float*)d_in[0];
    const float* w_qkv  = (const float*)d_in[1];
    const float* w_proj = (const float*)d_in[2];
    const float* b_proj = (const float*)d_in[3];
    float* out = (float*)d_out;
    (void)in_sizes; (void)n_in; (void)out_size;

    cudaFuncSetAttribute(gemm_tf32<0>,
                         cudaFuncAttributeMaxDynamicSharedMemorySize, GEMM_SMEM_BYTES);
    cudaFuncSetAttribute(gemm_tf32<1>,
                         cudaFuncAttributeMaxDynamicSharedMemorySize, GEMM_SMEM_BYTES);
    cudaFuncSetAttribute(attn_mma,
                         cudaFuncAttributeMaxDynamicSharedMemorySize, ATTN_SMEM_B);

    rope_table_kernel<<<256, 256>>>();
    gemm_tf32<0><<<dim3(N3_ / 128, M_ / 128), 256, GEMM_SMEM_BYTES>>>(x, w_qkv, nullptr, nullptr);
    attn_mma<<<dim3(T_ / 128, BH_), 256, ATTN_SMEM_B>>>();
    gemm_tf32<1><<<dim3(C_ / 128, M_ / 128), 256, GEMM_SMEM_BYTES>>>(nullptr, w_proj, b_proj, out);
}

// round 8
// speedup vs baseline: 2.1125x; 1.5632x over previous
#include <cuda_runtime.h>
#include <math.h>
#include <stdint.h>

#define B_  2
#define T_  2048
#define C_  1024
#define H_  16
#define D_  64
#define BH_ 32
#define M_  4096
#define N3_ 3072
#define K_  1024

// ---------------- scratch (__device__ globals; no allocs allowed) -----------
// q/k raw fp32 in [bh][d][t] (k-major for S-mma frags); v raw fp32 [bh][t][d].
__device__ float g_q[BH_*D_*T_];
__device__ float g_k[BH_*D_*T_];
__device__ float g_v[BH_*T_*D_];
__device__ float g_y[M_*C_];
__device__ float g_cos[T_*32], g_sin[T_*32];

// ---------------- helpers ----------------------------------------------------
__device__ __forceinline__ uint32_t smem_u32(const void* p) {
    uint32_t a;
    asm("{ .reg .u64 t; cvta.to.shared.u64 t, %1; cvt.u32.u64 %0, t; }"
        : "=r"(a) : "l"(p));
    return a;
}

// split two fp32 into packed bf16 hi-pair and lo-pair (v0 -> low half)
__device__ __forceinline__ void split2bf(float v0, float v1,
                                         uint32_t& h, uint32_t& l) {
    uint32_t hp;
    asm("cvt.rn.bf16x2.f32 %0, %1, %2;" : "=r"(hp) : "f"(v1), "f"(v0));
    float h0 = __uint_as_float(hp << 16);
    float h1 = __uint_as_float(hp & 0xFFFF0000u);
    float r0 = v0 - h0;
    float r1 = v1 - h1;
    asm("cvt.rn.bf16x2.f32 %0, %1, %2;" : "=r"(l) : "f"(r1), "f"(r0));
    h = hp;
}

__device__ __forceinline__ void mma_bf16(float c[4], const uint32_t a[4],
                                         const uint32_t b[2]) {
    asm volatile(
        "mma.sync.aligned.m16n8k16.row.col.f32.bf16.bf16.f32 "
        "{%0,%1,%2,%3}, {%4,%5,%6,%7}, {%8,%9}, {%0,%1,%2,%3};"
        : "+f"(c[0]), "+f"(c[1]), "+f"(c[2]), "+f"(c[3])
        : "r"(a[0]), "r"(a[1]), "r"(a[2]), "r"(a[3]), "r"(b[0]), "r"(b[1]));
}

// fast exp2 on FMA/ALU pipes (no MUFU)
__device__ __forceinline__ float fexp2(float t) {
    t = fmaxf(t, -126.0f);
    float r = t + 12582912.0f;
    int   n = __float_as_int(r);
    float f = t - (r - 12582912.0f);
    float p = 1.33335581e-3f;
    p = fmaf(p, f, 9.61812911e-3f);
    p = fmaf(p, f, 5.55041087e-2f);
    p = fmaf(p, f, 2.40226507e-1f);
    p = fmaf(p, f, 6.93147180e-1f);
    p = fmaf(p, f, 1.0f);
    return __int_as_float(__float_as_int(p) + (n << 23));
}
#define L2E_ 1.4426950408889634f

__device__ __forceinline__ void cpa16(uint32_t s, const void* gp) {
    asm volatile("cp.async.cg.shared.global [%0], [%1], 16;" :: "r"(s), "l"(gp));
}
#define CP_COMMIT() asm volatile("cp.async.commit_group;" ::: "memory")
#define CP_WAIT1()  asm volatile("cp.async.wait_group 1;" ::: "memory")

// ---------------- RoPE table -------------------------------------------------
__global__ void rope_table_kernel() {
    int idx = blockIdx.x * 256 + threadIdx.x;   // 65536
    int t = idx >> 5, i = idx & 31;
    double inv = pow(10000.0, -(double)(2 * i) / 64.0);
    float ff = (float)t * (float)inv;
    double s, c;
    sincos((double)ff, &s, &c);
    g_cos[idx] = (float)c;
    g_sin[idx] = (float)s;
}

// ---------------- split-bf16 GEMM, raw-fp32 smem, cp.async double buffer ----
#define ASTR 36                       // A smem row stride [m][k]
#define AS_W (128 * ASTR)             // 4608 words
#define BSTR 132                      // B smem row stride [k][n]; 132%32=4
#define BS_W (32 * BSTR)              // 4224 words
#define STG_W (AS_W + BS_W)           // 8832 words / stage
#define GEMM_SMEM_BYTES (2 * STG_W * 4)  // 70,656 B

__device__ __forceinline__ void gemm_load_stage(
    uint32_t su, const float* __restrict__ A, const float* __restrict__ W,
    int m0, int n0, int kk, int N, int tid)
{
    const uint32_t bu = su + AS_W * 4;
    #pragma unroll
    for (int i = 0; i < 4; i++) {               // A: 128m x 32k, row-major
        int c = i * 256 + tid;
        int m = c >> 3, ch = c & 7;
        cpa16(su + (m * ASTR + ch * 4) * 4, A + (size_t)(m0 + m) * K_ + kk + ch * 4);
    }
    #pragma unroll
    for (int i = 0; i < 4; i++) {               // B: 32k x 128n, row-major
        int c = i * 256 + tid;
        int k = c >> 5, ch = c & 31;
        cpa16(bu + (k * BSTR + ch * 4) * 4, W + (size_t)(kk + k) * N + n0 + ch * 4);
    }
}

template <int MODE>
__global__ __launch_bounds__(256, 2) void gemm_bf16(
    const float* __restrict__ Ain, const float* __restrict__ W,
    const float* __restrict__ bias, float* __restrict__ out)
{
    const int N = MODE ? C_ : N3_;
    extern __shared__ float dsm[];
    const uint32_t sb = smem_u32(dsm);

    // device-side symbol (host-side g_y would be the host shadow address)
    const float* A = MODE ? (const float*)g_y : Ain;

    const int tid  = threadIdx.x;
    const int wid  = tid >> 5;
    const int lane = tid & 31;
    const int g  = lane >> 2;
    const int tq = lane & 3;
    const int wm = wid >> 2;
    const int wn = wid & 3;
    const int m0 = blockIdx.y * 128;
    const int n0 = blockIdx.x * 128;

    float acc[4][4][4] = {};

    gemm_load_stage(sb, A, W, m0, n0, 0, N, tid);
    CP_COMMIT();

    for (int kk = 0; kk < K_; kk += 32) {
        const int s = (kk >> 5) & 1;
        if (kk + 32 < K_)
            gemm_load_stage(sb + (uint32_t)(s ^ 1) * STG_W * 4, A, W, m0, n0,
                            kk + 32, N, tid);
        CP_COMMIT();
        CP_WAIT1();
        __syncthreads();

        const float* As = dsm + s * STG_W;
        const float* Bs = As + AS_W;

        #pragma unroll
        for (int ks = 0; ks < 2; ks++) {
            const int k0 = ks * 16;
            uint32_t ah[4][4], al[4][4], bh[4][2], bl[4][2];
            #pragma unroll
            for (int mi = 0; mi < 4; mi++) {
                int mb = wm * 64 + mi * 16 + g;
                float2 p;
                p = *(const float2*)(As + (size_t)mb * ASTR + k0 + 2*tq);
                split2bf(p.x, p.y, ah[mi][0], al[mi][0]);
                p = *(const float2*)(As + (size_t)(mb + 8) * ASTR + k0 + 2*tq);
                split2bf(p.x, p.y, ah[mi][1], al[mi][1]);
                p = *(const float2*)(As + (size_t)mb * ASTR + k0 + 2*tq + 8);
                split2bf(p.x, p.y, ah[mi][2], al[mi][2]);
                p = *(const float2*)(As + (size_t)(mb + 8) * ASTR + k0 + 2*tq + 8);
                split2bf(p.x, p.y, ah[mi][3], al[mi][3]);
            }
            #pragma unroll
            for (int ni = 0; ni < 4; ni++) {
                int nb = wn * 32 + ni * 8 + g;
                split2bf(Bs[(size_t)(k0 + 2*tq)     * BSTR + nb],
                         Bs[(size_t)(k0 + 2*tq + 1) * BSTR + nb],
                         bh[ni][0], bl[ni][0]);
                split2bf(Bs[(size_t)(k0 + 2*tq + 8) * BSTR + nb],
                         Bs[(size_t)(k0 + 2*tq + 9) * BSTR + nb],
                         bh[ni][1], bl[ni][1]);
            }
            #pragma unroll
            for (int mi = 0; mi < 4; mi++)
                #pragma unroll
                for (int ni = 0; ni < 4; ni++) {
                    mma_bf16(acc[mi][ni], ah[mi], bh[ni]);
                    mma_bf16(acc[mi][ni], al[mi], bh[ni]);
                    mma_bf16(acc[mi][ni], ah[mi], bl[ni]);
                }
        }
        __syncthreads();
    }

    // ------------- epilogue -------------
    #pragma unroll
    for (int mi = 0; mi < 4; mi++) {
        #pragma unroll
        for (int ni = 0; ni < 4; ni++) {
            const float* c = acc[mi][ni];
            int r0 = m0 + wm * 64 + mi * 16 + g;
            int nc = n0 + wn * 32 + ni * 8 + 2 * tq;
            #pragma unroll
            for (int half = 0; half < 2; half++) {
                int m = r0 + half * 8;
                float e = c[half * 2 + 0];
                float o = c[half * 2 + 1];
                if (MODE == 0) {
                    int b = m >> 11, t = m & 2047;
                    int sec = nc >> 10, cc = nc & 1023;
                    int hd = cc >> 6, d = cc & 63;       // d even
                    if (sec == 2) {
                        size_t vb = ((size_t)((b << 4) + hd) * T_ + t) * D_ + d;
                        *(float2*)(g_v + vb) = make_float2(e, o);
                    } else {
                        float co = g_cos[t * 32 + (d >> 1)];
                        float si = g_sin[t * 32 + (d >> 1)];
                        float oe = e * co - o * si;
                        float oo = e * si + o * co;
                        size_t base = ((size_t)((b << 4) + hd) * D_ + d) * T_ + t;
                        if (sec == 0) {
                            g_q[base]      = oe * 0.125f;
                            g_q[base + T_] = oo * 0.125f;
                        } else {
                            g_k[base]      = oe;
                            g_k[base + T_] = oo;
                        }
                    }
                } else {
                    float2 bv = *(const float2*)(bias + nc);
                    *(float2*)(out + (size_t)m * C_ + nc) =
                        make_float2(e + bv.x, o + bv.y);
                }
            }
        }
    }
}

// ---------------- MMA flash attention (split-bf16 k16) ----------------------
// 128 q x 64 kv per step; 8 warps each own m16. Q frags converted ONCE into
// registers. K/V raw fp32 in smem, double-buffered cp.async; split at frag
// load. P never touches smem: S-accumulator regs ARE the P A-fragments.
#define KSTR 68
#define KV_W (64 * KSTR)                  // one K or V tile, words
#define KVSTG_W (2 * KV_W)                // K+V per stage
#define ATTN_WORDS (2 * KVSTG_W)
#define ATTN_SMEM_B (ATTN_WORDS * 4)      // 69,632 B

__device__ __forceinline__ void attn_load_kv(
    uint32_t su, const float* __restrict__ gk, const float* __restrict__ gv,
    int kv0, int tid)
{
    const uint32_t vu = su + KV_W * 4;
    #pragma unroll
    for (int i = 0; i < 4; i++) {             // K: [d][t] 64x64
        int c = i * 256 + tid;
        int r = c >> 4, ch = c & 15;
        cpa16(su + (r * KSTR + ch * 4) * 4, gk + (size_t)r * T_ + kv0 + ch * 4);
    }
    #pragma unroll
    for (int i = 0; i < 4; i++) {             // V: [t][d] 64x64
        int c = i * 256 + tid;
        int r = c >> 4, ch = c & 15;
        cpa16(vu + (r * KSTR + ch * 4) * 4, gv + (size_t)(kv0 + r) * D_ + ch * 4);
    }
}

__global__ __launch_bounds__(256) void attn_mma() {
    extern __shared__ float swf[];
    const uint32_t sb = smem_u32(swf);
    const int tid  = threadIdx.x;
    const int wid  = tid >> 5, lane = tid & 31;
    const int g    = lane >> 2, tq = lane & 3;
    const int qt   = (int)gridDim.x - 1 - (int)blockIdx.x;  // heavy-first
    const int bh   = blockIdx.y;
    const int q0   = qt * 128;

    const float* gq = g_q + (size_t)bh * D_ * T_;
    const float* gk = g_k + (size_t)bh * D_ * T_;
    const float* gv = g_v + (size_t)bh * T_ * D_;

    // ---- Q fragments: load + split once, live in registers (k64 = 4 steps)
    const int mbq = wid * 16 + g;
    uint32_t qh[4][4], ql[4][4];
    #pragma unroll
    for (int ks = 0; ks < 4; ks++) {
        const int k0 = ks * 16;
        split2bf(gq[(size_t)(k0 + 2*tq)     * T_ + q0 + mbq],
                 gq[(size_t)(k0 + 2*tq + 1) * T_ + q0 + mbq],     qh[ks][0], ql[ks][0]);
        split2bf(gq[(size_t)(k0 + 2*tq)     * T_ + q0 + mbq + 8],
                 gq[(size_t)(k0 + 2*tq + 1) * T_ + q0 + mbq + 8], qh[ks][1], ql[ks][1]);
        split2bf(gq[(size_t)(k0 + 2*tq + 8) * T_ + q0 + mbq],
                 gq[(size_t)(k0 + 2*tq + 9) * T_ + q0 + mbq],     qh[ks][2], ql[ks][2]);
        split2bf(gq[(size_t)(k0 + 2*tq + 8) * T_ + q0 + mbq + 8],
                 gq[(size_t)(k0 + 2*tq + 9) * T_ + q0 + mbq + 8], qh[ks][3], ql[ks][3]);
    }

    float accO[8][4] = {};
    float mrow[2] = {-1e30f, -1e30f};
    float lrow[2] = {0.0f, 0.0f};

    const int nkv = 2 * qt + 2;
    const int wrow0 = q0 + wid * 16;

    attn_load_kv(sb, gk, gv, 0, tid);
    CP_COMMIT();

    for (int j = 0; j < nkv; j++) {
        const int s = j & 1;
        const int kv0 = j * 64;
        if (j + 1 < nkv)
            attn_load_kv(sb + (uint32_t)(s ^ 1) * KVSTG_W * 4, gk, gv, kv0 + 64, tid);
        CP_COMMIT();
        CP_WAIT1();
        __syncthreads();

        if (kv0 <= wrow0 + 15) {
            const float* Ks = swf + s * KVSTG_W;
            const float* Vs = Ks + KV_W;

            // ---- S = Q @ K^T ----
            float accS[8][4] = {};
            #pragma unroll
            for (int ks = 0; ks < 4; ks++) {
                const int k0 = ks * 16;
                #pragma unroll
                for (int nf = 0; nf < 8; nf++) {
                    const int nb = nf * 8 + g;
                    uint32_t kh[2], kl[2];
                    split2bf(Ks[(size_t)(k0 + 2*tq)     * KSTR + nb],
                             Ks[(size_t)(k0 + 2*tq + 1) * KSTR + nb], kh[0], kl[0]);
                    split2bf(Ks[(size_t)(k0 + 2*tq + 8) * KSTR + nb],
                             Ks[(size_t)(k0 + 2*tq + 9) * KSTR + nb], kh[1], kl[1]);
                    mma_bf16(accS[nf], qh[ks], kh);
                    mma_bf16(accS[nf], ql[ks], kh);
                    mma_bf16(accS[nf], qh[ks], kl);
                }
            }

            // ---- causal mask ----
            if (kv0 + 63 > wrow0) {
                #pragma unroll
                for (int nf = 0; nf < 8; nf++)
                    #pragma unroll
                    for (int r = 0; r < 4; r++) {
                        int row = wrow0 + g + (r >> 1) * 8;
                        int col = kv0 + nf * 8 + 2 * tq + (r & 1);
                        if (col > row) accS[nf][r] = -1e30f;
                    }
            }

            // ---- online softmax (fexp2, no MUFU) ----
            #pragma unroll
            for (int hh = 0; hh < 2; hh++) {
                float mx = -1e30f;
                #pragma unroll
                for (int nf = 0; nf < 8; nf++)
                    mx = fmaxf(mx, fmaxf(accS[nf][2*hh], accS[nf][2*hh+1]));
                mx = fmaxf(mx, __shfl_xor_sync(0xffffffffu, mx, 1));
                mx = fmaxf(mx, __shfl_xor_sync(0xffffffffu, mx, 2));
                float mn = fmaxf(mrow[hh], mx);
                float corr = fexp2((mrow[hh] - mn) * L2E_);
                mrow[hh] = mn;
                float mnL = mn * L2E_;
                float ps = 0.0f;
                #pragma unroll
                for (int nf = 0; nf < 8; nf++) {
                    float p0 = fexp2(fmaf(accS[nf][2*hh],   L2E_, -mnL));
                    float p1 = fexp2(fmaf(accS[nf][2*hh+1], L2E_, -mnL));
                    accS[nf][2*hh] = p0; accS[nf][2*hh+1] = p1;
                    ps += p0 + p1;
                }
                ps += __shfl_xor_sync(0xffffffffu, ps, 1);
                ps += __shfl_xor_sync(0xffffffffu, ps, 2);
                lrow[hh] = lrow[hh] * corr + ps;
                #pragma unroll
                for (int nf = 0; nf < 8; nf++) {
                    accO[nf][2*hh]   *= corr;
                    accO[nf][2*hh+1] *= corr;
                }
            }

            // ---- O += P @ V : P fragments come straight from accS regs ----
            #pragma unroll
            for (int ks = 0; ks < 4; ks++) {
                const int k0 = ks * 16;
                uint32_t ph[4], pl[4];
                split2bf(accS[2*ks][0],   accS[2*ks][1],   ph[0], pl[0]);
                split2bf(accS[2*ks][2],   accS[2*ks][3],   ph[1], pl[1]);
                split2bf(accS[2*ks+1][0], accS[2*ks+1][1], ph[2], pl[2]);
                split2bf(accS[2*ks+1][2], accS[2*ks+1][3], ph[3], pl[3]);
                #pragma unroll
                for (int nf = 0; nf < 8; nf++) {
                    const int nb = nf * 8 + g;
                    uint32_t vh[2], vl[2];
                    split2bf(Vs[(size_t)(k0 + 2*tq)     * KSTR + nb],
                             Vs[(size_t)(k0 + 2*tq + 1) * KSTR + nb], vh[0], vl[0]);
                    split2bf(Vs[(size_t)(k0 + 2*tq + 8) * KSTR + nb],
                             Vs[(size_t)(k0 + 2*tq + 9) * KSTR + nb], vh[1], vl[1]);
                    mma_bf16(accO[nf], ph, vh);
                    mma_bf16(accO[nf], pl, vh);
                    mma_bf16(accO[nf], ph, vl);
                }
            }
        }
        __syncthreads();
    }

    // ---- write y [B,T,C] ----
    const int b = bh >> 4, hd = bh & 15;
    #pragma unroll
    for (int hh = 0; hh < 2; hh++) {
        float inv = 1.0f / lrow[hh];
        int t = q0 + wid * 16 + g + hh * 8;
        float* yrow = g_y + (size_t)(b * T_ + t) * C_ + hd * 64;
        #pragma unroll
        for (int nf = 0; nf < 8; nf++)
            *(float2*)(yrow + nf * 8 + 2 * tq) =
                make_float2(accO[nf][2*hh] * inv, accO[nf][2*hh+1] * inv);
    }
}

// ---------------------------------------------------------------------------
extern "C" void kernel_launch(void* const* d_in, const int* in_sizes, int n_in,
                              void* d_out, int out_size)
{
    const float* x      = (const float*)d_in[0];
    const float* w_qkv  = (const float*)d_in[1];
    const float* w_proj = (const float*)d_in[2];
    const float* b_proj = (const float*)d_in[3];
    float* out = (float*)d_out;
    (void)in_sizes; (void)n_in; (void)out_size;

    cudaFuncSetAttribute(gemm_bf16<0>,
                         cudaFuncAttributeMaxDynamicSharedMemorySize, GEMM_SMEM_BYTES);
    cudaFuncSetAttribute(gemm_bf16<1>,
                         cudaFuncAttributeMaxDynamicSharedMemorySize, GEMM_SMEM_BYTES);
    cudaFuncSetAttribute(attn_mma,
                         cudaFuncAttributeMaxDynamicSharedMemorySize, ATTN_SMEM_B);

    rope_table_kernel<<<256, 256>>>();
    gemm_bf16<0><<<dim3(N3_ / 128, M_ / 128), 256, GEMM_SMEM_BYTES>>>(x, w_qkv, nullptr, nullptr);
    attn_mma<<<dim3(T_ / 128, BH_), 256, ATTN_SMEM_B>>>();
    gemm_bf16<1><<<dim3(C_ / 128, M_ / 128), 256, GEMM_SMEM_BYTES>>>(nullptr, w_proj, b_proj, out);
}

// round 9
// speedup vs baseline: 2.3528x; 1.1138x over previous
#include <cuda_runtime.h>
#include <math.h>
#include <stdint.h>

#define B_  2
#define T_  2048
#define C_  1024
#define H_  16
#define D_  64
#define BH_ 32
#define M_  4096
#define N3_ 3072
#define K_  1024

// ---------------- scratch (__device__ globals; no allocs allowed) -----------
// Packed bf16 hi/lo pairs along d: word idx = (bh*T + t)*32 + d/2
__device__ uint32_t g_qp_h[BH_*T_*32], g_qp_l[BH_*T_*32];
__device__ uint32_t g_kp_h[BH_*T_*32], g_kp_l[BH_*T_*32];
__device__ uint32_t g_vp_h[BH_*T_*32], g_vp_l[BH_*T_*32];  // bf16 pair (d,d+1) per word
__device__ float g_y[M_*C_];
__device__ float g_cos[T_*32], g_sin[T_*32];

// ---------------- helpers ----------------------------------------------------
__device__ __forceinline__ uint32_t smem_u32(const void* p) {
    uint32_t a;
    asm("{ .reg .u64 t; cvta.to.shared.u64 t, %1; cvt.u32.u64 %0, t; }"
        : "=r"(a) : "l"(p));
    return a;
}

// split two fp32 into packed bf16 hi-pair and lo-pair (v0 -> low half)
__device__ __forceinline__ void split2bf(float v0, float v1,
                                         uint32_t& h, uint32_t& l) {
    uint32_t hp;
    asm("cvt.rn.bf16x2.f32 %0, %1, %2;" : "=r"(hp) : "f"(v1), "f"(v0));
    float h0 = __uint_as_float(hp << 16);
    float h1 = __uint_as_float(hp & 0xFFFF0000u);
    float r0 = v0 - h0;
    float r1 = v1 - h1;
    asm("cvt.rn.bf16x2.f32 %0, %1, %2;" : "=r"(l) : "f"(r1), "f"(r0));
    h = hp;
}

__device__ __forceinline__ uint32_t prmt(uint32_t a, uint32_t b, uint32_t sel) {
    uint32_t r;
    asm("prmt.b32 %0, %1, %2, %3;" : "=r"(r) : "r"(a), "r"(b), "r"(sel));
    return r;
}

__device__ __forceinline__ void mma_bf16(float c[4], const uint32_t a[4],
                                         const uint32_t b[2]) {
    asm volatile(
        "mma.sync.aligned.m16n8k16.row.col.f32.bf16.bf16.f32 "
        "{%0,%1,%2,%3}, {%4,%5,%6,%7}, {%8,%9}, {%0,%1,%2,%3};"
        : "+f"(c[0]), "+f"(c[1]), "+f"(c[2]), "+f"(c[3])
        : "r"(a[0]), "r"(a[1]), "r"(a[2]), "r"(a[3]), "r"(b[0]), "r"(b[1]));
}

// fast exp2 on FMA/ALU pipes (no MUFU)
__device__ __forceinline__ float fexp2(float t) {
    t = fmaxf(t, -126.0f);
    float r = t + 12582912.0f;
    int   n = __float_as_int(r);
    float f = t - (r - 12582912.0f);
    float p = 1.33335581e-3f;
    p = fmaf(p, f, 9.61812911e-3f);
    p = fmaf(p, f, 5.55041087e-2f);
    p = fmaf(p, f, 2.40226507e-1f);
    p = fmaf(p, f, 6.93147180e-1f);
    p = fmaf(p, f, 1.0f);
    return __int_as_float(__float_as_int(p) + (n << 23));
}
#define L2E_ 1.4426950408889634f

__device__ __forceinline__ void cpa16(uint32_t s, const void* gp) {
    asm volatile("cp.async.cg.shared.global [%0], [%1], 16;" :: "r"(s), "l"(gp));
}
#define CP_COMMIT() asm volatile("cp.async.commit_group;" ::: "memory")
#define CP_WAIT1()  asm volatile("cp.async.wait_group 1;" ::: "memory")
#define CP_WAIT2()  asm volatile("cp.async.wait_group 2;" ::: "memory")

// ---------------- RoPE table -------------------------------------------------
__global__ void rope_table_kernel() {
    int idx = blockIdx.x * 256 + threadIdx.x;   // 65536
    int t = idx >> 5, i = idx & 31;
    double inv = pow(10000.0, -(double)(2 * i) / 64.0);
    float ff = (float)t * (float)inv;
    double s, c;
    sincos((double)ff, &s, &c);
    g_cos[idx] = (float)c;
    g_sin[idx] = (float)s;
}

// ---------------- split-bf16 GEMM, 4-stage k16 cp.async ring -----------------
#define ASTR 20                       // A smem row stride [m][k16+pad]
#define AS_W (128 * ASTR)             // 2560 words
#define BSTR 132                      // B smem row stride [k][n]
#define BS_W (16 * BSTR)              // 2112 words
#define STG_W (AS_W + BS_W)           // 4672 words / stage
#define NSTAGE 4
#define GEMM_SMEM_BYTES (NSTAGE * STG_W * 4)   // 74,752 B

__device__ __forceinline__ void gemm_load_stage(
    uint32_t su, const float* __restrict__ A, const float* __restrict__ W,
    int m0, int n0, int kk, int N, int tid)
{
    const uint32_t bu = su + AS_W * 4;
    #pragma unroll
    for (int i = 0; i < 2; i++) {               // A: 128m x 16k
        int c = i * 256 + tid;
        int m = c >> 2, ch = (c & 3) * 4;
        cpa16(su + (m * ASTR + ch) * 4, A + (size_t)(m0 + m) * K_ + kk + ch);
    }
    #pragma unroll
    for (int i = 0; i < 2; i++) {               // B: 16k x 128n
        int c = i * 256 + tid;
        int k = c >> 5, ch = (c & 31) * 4;
        cpa16(bu + (k * BSTR + ch) * 4, W + (size_t)(kk + k) * N + n0 + ch);
    }
}

template <int MODE>
__global__ __launch_bounds__(256, 2) void gemm_bf16(
    const float* __restrict__ Ain, const float* __restrict__ W,
    const float* __restrict__ bias, float* __restrict__ out)
{
    const int N = MODE ? C_ : N3_;
    extern __shared__ float dsm[];
    const uint32_t sb = smem_u32(dsm);

    // device-side symbol (host-side g_y would be the host shadow address)
    const float* A = MODE ? (const float*)g_y : Ain;

    const int tid  = threadIdx.x;
    const int wid  = tid >> 5;
    const int lane = tid & 31;
    const int g  = lane >> 2;
    const int tq = lane & 3;
    const int wm = wid >> 2;
    const int wn = wid & 3;
    const int m0 = blockIdx.y * 128;
    const int n0 = blockIdx.x * 128;

    float acc[4][4][4] = {};

    gemm_load_stage(sb, A, W, m0, n0, 0, N, tid);  CP_COMMIT();
    gemm_load_stage(sb + STG_W * 4, A, W, m0, n0, 16, N, tid);  CP_COMMIT();
    gemm_load_stage(sb + 2 * STG_W * 4, A, W, m0, n0, 32, N, tid);  CP_COMMIT();

    for (int j = 0; j < K_ / 16; j++) {
        CP_WAIT2();
        __syncthreads();
        if (j + 3 < K_ / 16)
            gemm_load_stage(sb + (uint32_t)((j + 3) & 3) * STG_W * 4, A, W,
                            m0, n0, (j + 3) * 16, N, tid);
        CP_COMMIT();

        const float* As = dsm + (j & 3) * STG_W;
        const float* Bs = As + AS_W;

        uint32_t ah[4][4], al[4][4], bh[4][2], bl[4][2];
        #pragma unroll
        for (int mi = 0; mi < 4; mi++) {
            int mb = wm * 64 + mi * 16 + g;
            float2 p;
            p = *(const float2*)(As + (size_t)mb * ASTR + 2*tq);
            split2bf(p.x, p.y, ah[mi][0], al[mi][0]);
            p = *(const float2*)(As + (size_t)(mb + 8) * ASTR + 2*tq);
            split2bf(p.x, p.y, ah[mi][1], al[mi][1]);
            p = *(const float2*)(As + (size_t)mb * ASTR + 2*tq + 8);
            split2bf(p.x, p.y, ah[mi][2], al[mi][2]);
            p = *(const float2*)(As + (size_t)(mb + 8) * ASTR + 2*tq + 8);
            split2bf(p.x, p.y, ah[mi][3], al[mi][3]);
        }
        #pragma unroll
        for (int ni = 0; ni < 4; ni++) {
            int nb = wn * 32 + ni * 8 + g;
            split2bf(Bs[(size_t)(2*tq)     * BSTR + nb],
                     Bs[(size_t)(2*tq + 1) * BSTR + nb], bh[ni][0], bl[ni][0]);
            split2bf(Bs[(size_t)(2*tq + 8) * BSTR + nb],
                     Bs[(size_t)(2*tq + 9) * BSTR + nb], bh[ni][1], bl[ni][1]);
        }
        #pragma unroll
        for (int mi = 0; mi < 4; mi++)
            #pragma unroll
            for (int ni = 0; ni < 4; ni++) {
                mma_bf16(acc[mi][ni], ah[mi], bh[ni]);
                mma_bf16(acc[mi][ni], al[mi], bh[ni]);
                mma_bf16(acc[mi][ni], ah[mi], bl[ni]);
            }
    }

    // ------------- epilogue -------------
    #pragma unroll
    for (int mi = 0; mi < 4; mi++) {
        #pragma unroll
        for (int ni = 0; ni < 4; ni++) {
            const float* c = acc[mi][ni];
            int r0 = m0 + wm * 64 + mi * 16 + g;
            int nc = n0 + wn * 32 + ni * 8 + 2 * tq;
            #pragma unroll
            for (int half = 0; half < 2; half++) {
                int m = r0 + half * 8;
                float e = c[half * 2 + 0];
                float o = c[half * 2 + 1];
                if (MODE == 0) {
                    int b = m >> 11, t = m & 2047;
                    int sec = nc >> 10, cc = nc & 1023;
                    int hd = cc >> 6, d = cc & 63;       // d even
                    size_t idx = ((size_t)((b << 4) + hd) * T_ + t) * 32 + (d >> 1);
                    uint32_t ph, pl;
                    if (sec == 2) {
                        split2bf(e, o, ph, pl);
                        g_vp_h[idx] = ph; g_vp_l[idx] = pl;
                    } else {
                        float co = g_cos[t * 32 + (d >> 1)];
                        float si = g_sin[t * 32 + (d >> 1)];
                        float oe = e * co - o * si;
                        float oo = e * si + o * co;
                        if (sec == 0) {
                            split2bf(oe * 0.125f, oo * 0.125f, ph, pl);
                            g_qp_h[idx] = ph; g_qp_l[idx] = pl;
                        } else {
                            split2bf(oe, oo, ph, pl);
                            g_kp_h[idx] = ph; g_kp_l[idx] = pl;
                        }
                    }
                } else {
                    float2 bv = *(const float2*)(bias + nc);
                    *(float2*)(out + (size_t)m * C_ + nc) =
                        make_float2(e + bv.x, o + bv.y);
                }
            }
        }
    }
}

// ---------------- MMA flash attention (pre-split bf16, repacked V) ----------
// 128 q x 64 kv per step, 8 warps each own m16. K arrives packed (d-pairs)
// via cp.async — zero conversion. V arrives packed-along-d; a cooperative
// PRMT repack builds Vp[d][kvpair]. P frags come straight from accS regs.
#define KPSTR 36
#define KPW   (64 * KPSTR)                 // 2304 words per array
#define VRSTR 36
#define VRW   (64 * VRSTR)                 // 2304 words per array
#define ASTG_W (2 * KPW + 2 * VRW)         // 9216 words per stage
// stage offsets (words): KPH=0, KPL=KPW, VRH=2*KPW, VRL=2*KPW+VRW
#define VP_BASE (2 * ASTG_W)               // 18432
#define VPSTG_W (2 * KPW)                  // 4608 per Vp stage (hi+lo)
#define ATTN_WORDS (VP_BASE + 2 * VPSTG_W) // 27648
#define ATTN_SMEM_B (ATTN_WORDS * 4)       // 110,592 B

__device__ __forceinline__ void attn_load_stage(
    uint32_t su, const uint32_t* __restrict__ kph,
    const uint32_t* __restrict__ kpl, const uint32_t* __restrict__ vph,
    const uint32_t* __restrict__ vpl, int kv0, int tid)
{
    #pragma unroll
    for (int i = 0; i < 2; i++) {    // Kp hi: 64 rows x 32 words
        int c = i * 256 + tid;
        int r = c >> 3, ch = (c & 7) * 4;
        cpa16(su + (r * KPSTR + ch) * 4, kph + (size_t)(kv0 + r) * 32 + ch);
    }
    #pragma unroll
    for (int i = 0; i < 2; i++) {    // Kp lo
        int c = i * 256 + tid;
        int r = c >> 3, ch = (c & 7) * 4;
        cpa16(su + (KPW + r * KPSTR + ch) * 4, kpl + (size_t)(kv0 + r) * 32 + ch);
    }
    #pragma unroll
    for (int i = 0; i < 2; i++) {    // V raw hi (packed along d)
        int c = i * 256 + tid;
        int r = c >> 3, ch = (c & 7) * 4;
        cpa16(su + (2 * KPW + r * VRSTR + ch) * 4, vph + (size_t)(kv0 + r) * 32 + ch);
    }
    #pragma unroll
    for (int i = 0; i < 2; i++) {    // V raw lo
        int c = i * 256 + tid;
        int r = c >> 3, ch = (c & 7) * 4;
        cpa16(su + (2 * KPW + VRW + r * VRSTR + ch) * 4, vpl + (size_t)(kv0 + r) * 32 + ch);
    }
}

__global__ __launch_bounds__(256, 2) void attn_mma() {
    extern __shared__ uint32_t sw[];
    const uint32_t sb = smem_u32(sw);
    const int tid  = threadIdx.x;
    const int wid  = tid >> 5, lane = tid & 31;
    const int g    = lane >> 2, tq = lane & 3;
    const int qt   = (int)gridDim.x - 1 - (int)blockIdx.x;  // heavy-first
    const int bh   = blockIdx.y;
    const int q0   = qt * 128;

    const uint32_t* kph = g_kp_h + (size_t)bh * T_ * 32;
    const uint32_t* kpl = g_kp_l + (size_t)bh * T_ * 32;
    const uint32_t* vph = g_vp_h + (size_t)bh * T_ * 32;
    const uint32_t* vpl = g_vp_l + (size_t)bh * T_ * 32;

    // ---- Q fragments straight from packed gmem (no conversion at all) ----
    const int wrow0 = q0 + wid * 16;
    uint32_t qh[4][4], ql[4][4];
    {
        const size_t r0 = ((size_t)bh * T_ + wrow0 + g) * 32;
        const size_t r8 = r0 + 8 * 32;
        #pragma unroll
        for (int ks = 0; ks < 4; ks++) {
            int cp0 = 8 * ks + tq;
            qh[ks][0] = g_qp_h[r0 + cp0];     ql[ks][0] = g_qp_l[r0 + cp0];
            qh[ks][1] = g_qp_h[r8 + cp0];     ql[ks][1] = g_qp_l[r8 + cp0];
            qh[ks][2] = g_qp_h[r0 + cp0 + 4]; ql[ks][2] = g_qp_l[r0 + cp0 + 4];
            qh[ks][3] = g_qp_h[r8 + cp0 + 4]; ql[ks][3] = g_qp_l[r8 + cp0 + 4];
        }
    }

    float accO[8][4] = {};
    float mrow[2] = {-1e30f, -1e30f};
    float lrow[2] = {0.0f, 0.0f};
    const int nkv = 2 * qt + 2;
    const int xorv = (g >> 1) & 3;

    attn_load_stage(sb, kph, kpl, vph, vpl, 0, tid);  CP_COMMIT();
    if (nkv > 1) attn_load_stage(sb + ASTG_W * 4, kph, kpl, vph, vpl, 64, tid);
    CP_COMMIT();

    for (int j = 0; j < nkv; j++) {
        const int s = j & 1;
        const int kv0 = j * 64;
        const uint32_t* Kh = sw + s * ASTG_W;
        const uint32_t* Kl = Kh + KPW;
        const uint32_t* Vr_h = Kh + 2 * KPW;
        const uint32_t* Vr_l = Vr_h + VRW;
        uint32_t* Vp_h = sw + VP_BASE + s * VPSTG_W;
        uint32_t* Vp_l = Vp_h + KPW;

        CP_WAIT1();
        __syncthreads();

        // ---- cooperative V repack: Vp[d][kvp ^ (dw&3)] via PRMT ----
        {
            const int dw = (lane >> 3) + 4 * wid;       // 0..31
            #pragma unroll
            for (int i = 0; i < 4; i++) {
                int kvp = (lane & 7) + 8 * i;
                int c = kvp ^ (dw & 3);
                uint32_t w0 = Vr_h[(2 * kvp) * VRSTR + dw];
                uint32_t w1 = Vr_h[(2 * kvp + 1) * VRSTR + dw];
                Vp_h[(2 * dw) * KPSTR + c]     = prmt(w0, w1, 0x5410);
                Vp_h[(2 * dw + 1) * KPSTR + c] = prmt(w0, w1, 0x7632);
                w0 = Vr_l[(2 * kvp) * VRSTR + dw];
                w1 = Vr_l[(2 * kvp + 1) * VRSTR + dw];
                Vp_l[(2 * dw) * KPSTR + c]     = prmt(w0, w1, 0x5410);
                Vp_l[(2 * dw + 1) * KPSTR + c] = prmt(w0, w1, 0x7632);
            }
        }
        __syncthreads();

        if (kv0 <= wrow0 + 15) {
            // ---- S = Q @ K^T (K frags: pure LDS, zero conversion) ----
            float accS[8][4] = {};
            #pragma unroll
            for (int ks = 0; ks < 4; ks++) {
                const int cp = 8 * ks + tq;
                #pragma unroll
                for (int nf = 0; nf < 8; nf++) {
                    const int nb = nf * 8 + g;
                    uint32_t kh[2], kl[2];
                    kh[0] = Kh[nb * KPSTR + cp];     kl[0] = Kl[nb * KPSTR + cp];
                    kh[1] = Kh[nb * KPSTR + cp + 4]; kl[1] = Kl[nb * KPSTR + cp + 4];
                    mma_bf16(accS[nf], qh[ks], kh);
                    mma_bf16(accS[nf], ql[ks], kh);
                    mma_bf16(accS[nf], qh[ks], kl);
                }
            }

            // ---- causal mask ----
            if (kv0 + 63 > wrow0) {
                #pragma unroll
                for (int nf = 0; nf < 8; nf++)
                    #pragma unroll
                    for (int r = 0; r < 4; r++) {
                        int row = wrow0 + g + (r >> 1) * 8;
                        int col = kv0 + nf * 8 + 2 * tq + (r & 1);
                        if (col > row) accS[nf][r] = -1e30f;
                    }
            }

            // ---- online softmax (fexp2, no MUFU) ----
            #pragma unroll
            for (int hh = 0; hh < 2; hh++) {
                float mx = -1e30f;
                #pragma unroll
                for (int nf = 0; nf < 8; nf++)
                    mx = fmaxf(mx, fmaxf(accS[nf][2*hh], accS[nf][2*hh+1]));
                mx = fmaxf(mx, __shfl_xor_sync(0xffffffffu, mx, 1));
                mx = fmaxf(mx, __shfl_xor_sync(0xffffffffu, mx, 2));
                float mn = fmaxf(mrow[hh], mx);
                float corr = fexp2((mrow[hh] - mn) * L2E_);
                mrow[hh] = mn;
                float mnL = mn * L2E_;
                float ps = 0.0f;
                #pragma unroll
                for (int nf = 0; nf < 8; nf++) {
                    float p0 = fexp2(fmaf(accS[nf][2*hh],   L2E_, -mnL));
                    float p1 = fexp2(fmaf(accS[nf][2*hh+1], L2E_, -mnL));
                    accS[nf][2*hh] = p0; accS[nf][2*hh+1] = p1;
                    ps += p0 + p1;
                }
                ps += __shfl_xor_sync(0xffffffffu, ps, 1);
                ps += __shfl_xor_sync(0xffffffffu, ps, 2);
                lrow[hh] = lrow[hh] * corr + ps;
                #pragma unroll
                for (int nf = 0; nf < 8; nf++) {
                    accO[nf][2*hh]   *= corr;
                    accO[nf][2*hh+1] *= corr;
                }
            }

            // ---- O += P @ V : P frags from accS regs, V frags pure LDS ----
            #pragma unroll
            for (int ks = 0; ks < 4; ks++) {
                uint32_t ph[4], pl[4];
                split2bf(accS[2*ks][0],   accS[2*ks][1],   ph[0], pl[0]);
                split2bf(accS[2*ks][2],   accS[2*ks][3],   ph[1], pl[1]);
                split2bf(accS[2*ks+1][0], accS[2*ks+1][1], ph[2], pl[2]);
                split2bf(accS[2*ks+1][2], accS[2*ks+1][3], ph[3], pl[3]);
                const int c0 = (8 * ks + tq) ^ xorv;
                const int c1 = (8 * ks + tq + 4) ^ xorv;
                #pragma unroll
                for (int nf = 0; nf < 8; nf++) {
                    const int nb = nf * 8 + g;
                    uint32_t vh[2], vl[2];
                    vh[0] = Vp_h[nb * KPSTR + c0]; vl[0] = Vp_l[nb * KPSTR + c0];
                    vh[1] = Vp_h[nb * KPSTR + c1]; vl[1] = Vp_l[nb * KPSTR + c1];
                    mma_bf16(accO[nf], ph, vh);
                    mma_bf16(accO[nf], pl, vh);
                    mma_bf16(accO[nf], ph, vl);
                }
            }
        }
        __syncthreads();   // all reads of raw stage s done before refill

        if (j + 2 < nkv)
            attn_load_stage(sb + (uint32_t)s * ASTG_W * 4, kph, kpl, vph, vpl,
                            kv0 + 128, tid);
        CP_COMMIT();
    }

    // ---- write y [B,T,C] ----
    const int b = bh >> 4, hd = bh & 15;
    #pragma unroll
    for (int hh = 0; hh < 2; hh++) {
        float inv = 1.0f / lrow[hh];
        int t = q0 + wid * 16 + g + hh * 8;
        float* yrow = g_y + (size_t)(b * T_ + t) * C_ + hd * 64;
        #pragma unroll
        for (int nf = 0; nf < 8; nf++)
            *(float2*)(yrow + nf * 8 + 2 * tq) =
                make_float2(accO[nf][2*hh] * inv, accO[nf][2*hh+1] * inv);
    }
}

// ---------------------------------------------------------------------------
extern "C" void kernel_launch(void* const* d_in, const int* in_sizes, int n_in,
                              void* d_out, int out_size)
{
    const float* x      = (const float*)d_in[0];
    const float* w_qkv  = (const float*)d_in[1];
    const float* w_proj = (const float*)d_in[2];
    const float* b_proj = (const float*)d_in[3];
    float* out = (float*)d_out;
    (void)in_sizes; (void)n_in; (void)out_size;

    cudaFuncSetAttribute(gemm_bf16<0>,
                         cudaFuncAttributeMaxDynamicSharedMemorySize, GEMM_SMEM_BYTES);
    cudaFuncSetAttribute(gemm_bf16<1>,
                         cudaFuncAttributeMaxDynamicSharedMemorySize, GEMM_SMEM_BYTES);
    cudaFuncSetAttribute(attn_mma,
                         cudaFuncAttributeMaxDynamicSharedMemorySize, ATTN_SMEM_B);

    rope_table_kernel<<<256, 256>>>();
    gemm_bf16<0><<<dim3(N3_ / 128, M_ / 128), 256, GEMM_SMEM_BYTES>>>(x, w_qkv, nullptr, nullptr);
    attn_mma<<<dim3(T_ / 128, BH_), 256, ATTN_SMEM_B>>>();
    gemm_bf16<1><<<dim3(C_ / 128, M_ / 128), 256, GEMM_SMEM_BYTES>>>(nullptr, w_proj, b_proj, out);
}